// round 2
// baseline (speedup 1.0000x reference)
#include <cuda_runtime.h>
#include <math.h>

// ---------------- problem constants ----------------
#define NN   4096
#define EE   65536
#define IND  512
#define HDIM 256
#define QD   256
#define NHD  8
#define HD   32
#define OUTD 10
#define LL   2
#define MW   (NN/32)   // mask words per row

// ---------------- static scratch (device globals; no runtime alloc) ----------------
__device__ float    g_h   [NN*HDIM];
__device__ float    g_Qt  [NN*QD];
__device__ float    g_Kt  [NN*QD];
__device__ float    g_Q   [NN*QD];
__device__ float    g_K   [NN*QD];
__device__ float    g_V   [NN*QD];
__device__ float    g_S   [(size_t)NN*NN];     // 64MB, reused: graph scores + per-head MHA scores
__device__ float    g_gatt[NN*QD];
__device__ float    g_mq  [NN*QD];
__device__ float    g_mk  [NN*QD];
__device__ float    g_mv  [NN*QD];
__device__ float    g_mo  [NN*QD];
__device__ float    g_mha [NN*QD];
__device__ float    g_eA  [NN*QD];
__device__ float    g_eB  [NN*QD];
__device__ float    g_m1  [(size_t)EE*QD];     // 64MB (also reused for m3)
__device__ float    g_m2  [(size_t)EE*QD];     // 64MB
__device__ unsigned g_mask[(size_t)NN*MW];
__device__ float    g_agg [NN*HDIM];
__device__ float    g_pool[2*HDIM];
__device__ float    g_z   [HDIM];

// ---------------- generic tiled SGEMM ----------------
// C[M,N] = act( A[M,K] * op(B) + bias ),  op(B)=B [K,N] or B^T (B stored [N,K])
// act: 0=none, 1=relu
template<int TRANSB>
__global__ void sgemm_k(const float* __restrict__ A, int lda,
                        const float* __restrict__ B, int ldb,
                        float* __restrict__ C, int ldc,
                        int M, int N, int K,
                        const float* __restrict__ bias, int act)
{
    __shared__ float As[16][65];
    __shared__ float Bs[16][65];

    const int tid = threadIdx.x;          // 256 threads
    const int tx  = tid & 15;
    const int ty  = tid >> 4;
    const int m0  = blockIdx.y * 64;
    const int n0  = blockIdx.x * 64;

    float acc[4][4];
#pragma unroll
    for (int i = 0; i < 4; i++)
#pragma unroll
        for (int j = 0; j < 4; j++) acc[i][j] = 0.f;

    for (int k0 = 0; k0 < K; k0 += 16) {
        // load A tile: As[k][m] = A[m0+m][k0+k]
#pragma unroll
        for (int i = 0; i < 4; i++) {
            int e = tid + i * 256;
            int m = e >> 4, k = e & 15;
            int gm = m0 + m, gk = k0 + k;
            As[k][m] = (gm < M && gk < K) ? A[(size_t)gm * lda + gk] : 0.f;
        }
        // load B tile: Bs[k][n] = op(B)[k0+k][n0+n]
#pragma unroll
        for (int i = 0; i < 4; i++) {
            int e = tid + i * 256;
            int k, n;
            if (TRANSB) { k = e & 15; n = e >> 4; }
            else        { k = e >> 6; n = e & 63; }
            int gk = k0 + k, gn = n0 + n;
            float v = 0.f;
            if (gn < N && gk < K)
                v = TRANSB ? B[(size_t)gn * ldb + gk] : B[(size_t)gk * ldb + gn];
            Bs[k][n] = v;
        }
        __syncthreads();
#pragma unroll
        for (int k = 0; k < 16; k++) {
            float ra[4], rb[4];
#pragma unroll
            for (int i = 0; i < 4; i++) ra[i] = As[k][ty * 4 + i];
#pragma unroll
            for (int j = 0; j < 4; j++) rb[j] = Bs[k][tx * 4 + j];
#pragma unroll
            for (int i = 0; i < 4; i++)
#pragma unroll
                for (int j = 0; j < 4; j++)
                    acc[i][j] = fmaf(ra[i], rb[j], acc[i][j]);
        }
        __syncthreads();
    }

#pragma unroll
    for (int i = 0; i < 4; i++) {
        int gm = m0 + ty * 4 + i;
        if (gm >= M) continue;
#pragma unroll
        for (int j = 0; j < 4; j++) {
            int gn = n0 + tx * 4 + j;
            if (gn >= N) continue;
            float v = acc[i][j];
            if (bias) v += bias[gn];
            if (act == 1) v = fmaxf(v, 0.f);
            C[(size_t)gm * ldc + gn] = v;
        }
    }
}

// ---------------- elementwise / reduction kernels ----------------
__global__ void zero_u32_k(unsigned* __restrict__ p, int n) {
    int i = blockIdx.x * blockDim.x + threadIdx.x;
    if (i < n) p[i] = 0u;
}
__global__ void zero_f32_k(float* __restrict__ p, int n) {
    int i = blockIdx.x * blockDim.x + threadIdx.x;
    if (i < n) p[i] = 0.f;
}
__global__ void build_mask_k(const int* __restrict__ ei, unsigned* __restrict__ mask) {
    int e = blockIdx.x * blockDim.x + threadIdx.x;
    if (e >= EE) return;
    int s = ei[e], t = ei[EE + e];
    atomicOr(&mask[(size_t)s * MW + (t >> 5)], 1u << (t & 31));
}
__global__ void add_ce_k(float* __restrict__ Q, float* __restrict__ K,
                         const float* __restrict__ ce, const int* __restrict__ ct) {
    int idx = blockIdx.x * blockDim.x + threadIdx.x;
    if (idx >= NN * QD) return;
    int i = idx >> 8, j = idx & 255;
    float v = 0.1f * ce[ct[i] * QD + j];
    Q[idx] += v;
    K[idx] += v;
}

// row softmax with graph mask (scale applied pre-mask; masked -> -1e9 like reference)
__global__ void masked_softmax_k(float* __restrict__ S, const unsigned* __restrict__ mask, float scale) {
    int r = blockIdx.x, t = threadIdx.x;
    const unsigned* mrow = mask + (size_t)r * MW;
    float* row = S + (size_t)r * NN;
    __shared__ float red[256];

    float mx = -3.4e38f;
    for (int c = t; c < NN; c += 256) {
        bool bit = (mrow[c >> 5] >> (c & 31)) & 1u;
        float v = bit ? row[c] * scale : -1e9f;
        mx = fmaxf(mx, v);
    }
    red[t] = mx; __syncthreads();
    for (int s = 128; s > 0; s >>= 1) { if (t < s) red[t] = fmaxf(red[t], red[t + s]); __syncthreads(); }
    mx = red[0]; __syncthreads();

    float sum = 0.f;
    for (int c = t; c < NN; c += 256) {
        bool bit = (mrow[c >> 5] >> (c & 31)) & 1u;
        float v = bit ? row[c] * scale : -1e9f;
        float e = __expf(v - mx);
        row[c] = e;
        sum += e;
    }
    red[t] = sum; __syncthreads();
    for (int s = 128; s > 0; s >>= 1) { if (t < s) red[t] += red[t + s]; __syncthreads(); }
    float inv = 1.f / red[0];
    for (int c = t; c < NN; c += 256) row[c] *= inv;
}

__global__ void softmax_k(float* __restrict__ S, float scale) {
    int r = blockIdx.x, t = threadIdx.x;
    float* row = S + (size_t)r * NN;
    __shared__ float red[256];

    float mx = -3.4e38f;
    for (int c = t; c < NN; c += 256) mx = fmaxf(mx, row[c] * scale);
    red[t] = mx; __syncthreads();
    for (int s = 128; s > 0; s >>= 1) { if (t < s) red[t] = fmaxf(red[t], red[t + s]); __syncthreads(); }
    mx = red[0]; __syncthreads();

    float sum = 0.f;
    for (int c = t; c < NN; c += 256) {
        float e = __expf(row[c] * scale - mx);
        row[c] = e;
        sum += e;
    }
    red[t] = sum; __syncthreads();
    for (int s = 128; s > 0; s >>= 1) { if (t < s) red[t] += red[t + s]; __syncthreads(); }
    float inv = 1.f / red[0];
    for (int c = t; c < NN; c += 256) row[c] *= inv;
}

// m1[e] = relu(eA[tgt[e]] + eB[src[e]] + bm1)
__global__ void edge_m1_k(const float* __restrict__ eA, const float* __restrict__ eB,
                          const int* __restrict__ ei, const float* __restrict__ bm1,
                          float* __restrict__ m1) {
    int idx = blockIdx.x * blockDim.x + threadIdx.x;
    if (idx >= EE * QD) return;
    int e = idx >> 8, j = idx & 255;
    int t = ei[EE + e], s = ei[e];
    m1[idx] = fmaxf(eA[(size_t)t * QD + j] + eB[(size_t)s * QD + j] + bm1[j], 0.f);
}

__global__ void scatter_k(const float* __restrict__ m3, const int* __restrict__ ei,
                          float* __restrict__ agg) {
    int idx = blockIdx.x * blockDim.x + threadIdx.x;
    if (idx >= EE * QD) return;
    int e = idx >> 8, j = idx & 255;
    atomicAdd(&agg[(size_t)ei[EE + e] * HDIM + j], m3[idx]);
}

// h = LN(res + agg + mha + gatt) * g + b   (in-place on h; one block per row, H=256 threads)
__global__ void combine_ln_k(float* __restrict__ h, const float* __restrict__ agg,
                             const float* __restrict__ mha, const float* __restrict__ gatt,
                             const float* __restrict__ g, const float* __restrict__ b) {
    int r = blockIdx.x, j = threadIdx.x;
    size_t idx = (size_t)r * HDIM + j;
    float v = h[idx] + agg[idx] + mha[idx] + gatt[idx];
    __shared__ float red[HDIM];
    red[j] = v; __syncthreads();
    for (int s = 128; s > 0; s >>= 1) { if (j < s) red[j] += red[j + s]; __syncthreads(); }
    float mu = red[0] * (1.f / HDIM);
    __syncthreads();
    float d = v - mu;
    red[j] = d * d; __syncthreads();
    for (int s = 128; s > 0; s >>= 1) { if (j < s) red[j] += red[j + s]; __syncthreads(); }
    float var = red[0] * (1.f / HDIM);
    h[idx] = d * rsqrtf(var + 1e-5f) * g[j] + b[j];
}

// pooled = concat(mean(h,0), max(h,0))
__global__ void pool_k(const float* __restrict__ h, float* __restrict__ pool) {
    int c = blockIdx.x, t = threadIdx.x;
    __shared__ float red[256];
    if (c < HDIM) {
        float s = 0.f;
        for (int r = t; r < NN; r += 256) s += h[(size_t)r * HDIM + c];
        red[t] = s; __syncthreads();
        for (int sh = 128; sh > 0; sh >>= 1) { if (t < sh) red[t] += red[t + sh]; __syncthreads(); }
        if (t == 0) pool[c] = red[0] * (1.f / NN);
    } else {
        int cc = c - HDIM;
        float m = -3.4e38f;
        for (int r = t; r < NN; r += 256) m = fmaxf(m, h[(size_t)r * HDIM + cc]);
        red[t] = m; __syncthreads();
        for (int sh = 128; sh > 0; sh >>= 1) { if (t < sh) red[t] = fmaxf(red[t], red[t + sh]); __syncthreads(); }
        if (t == 0) pool[c] = red[0];
    }
}

__global__ void fc1_k(const float* __restrict__ pool, const float* __restrict__ W,
                      const float* __restrict__ b, float* __restrict__ z) {
    int o = blockIdx.x, t = threadIdx.x;
    __shared__ float red[256];
    float s = 0.f;
    for (int i = t; i < 2 * HDIM; i += 256) s += pool[i] * W[(size_t)i * HDIM + o];
    red[t] = s; __syncthreads();
    for (int sh = 128; sh > 0; sh >>= 1) { if (t < sh) red[t] += red[t + sh]; __syncthreads(); }
    if (t == 0) z[o] = fmaxf(red[0] + b[o], 0.f);
}

__global__ void fc2_k(const float* __restrict__ z, const float* __restrict__ W,
                      const float* __restrict__ b, float* __restrict__ out) {
    int o = blockIdx.x, t = threadIdx.x;
    __shared__ float red[256];
    float s = 0.f;
    for (int i = t; i < HDIM; i += 256) s += z[i] * W[(size_t)i * OUTD + o];
    red[t] = s; __syncthreads();
    for (int sh = 128; sh > 0; sh >>= 1) { if (t < sh) red[t] += red[t + sh]; __syncthreads(); }
    if (t == 0) out[o] = red[0] + b[o];
}

// ---------------- host side ----------------
static void gemm(const float* A, int lda, const float* B, int ldb,
                 float* C, int ldc, int M, int N, int K,
                 const float* bias, int act, bool transB) {
    dim3 grid((N + 63) / 64, (M + 63) / 64), blk(256);
    if (transB) sgemm_k<1><<<grid, blk>>>(A, lda, B, ldb, C, ldc, M, N, K, bias, act);
    else        sgemm_k<0><<<grid, blk>>>(A, lda, B, ldb, C, ldc, M, N, K, bias, act);
}

static float* sym(const void* s) {
    void* p = nullptr;
    cudaGetSymbolAddress(&p, (const void*)s);
    return (float*)p;
}

extern "C" void kernel_launch(void* const* d_in, const int* in_sizes, int n_in,
                              void* d_out, int out_size) {
    // inputs (metadata order)
    const float* x    = (const float*)d_in[0];
    const int*   ei   = (const int*)  d_in[1];
    const int*   ct   = (const int*)  d_in[2];
    const float* Wi   = (const float*)d_in[3];
    const float* bi   = (const float*)d_in[4];
    const float* Wq   = (const float*)d_in[5];
    const float* bq   = (const float*)d_in[6];
    const float* Wk   = (const float*)d_in[7];
    const float* bk   = (const float*)d_in[8];
    const float* Wv   = (const float*)d_in[9];
    const float* bv   = (const float*)d_in[10];
    const float* Bc   = (const float*)d_in[11];
    const float* cemb = (const float*)d_in[12];
    const float* Win  = (const float*)d_in[13];
    const float* binp = (const float*)d_in[14];
    const float* Wo   = (const float*)d_in[15];
    const float* bo   = (const float*)d_in[16];
    const float* Wm1  = (const float*)d_in[17];
    const float* bm1  = (const float*)d_in[18];
    const float* Wm2  = (const float*)d_in[19];
    const float* bm2  = (const float*)d_in[20];
    const float* Wm3  = (const float*)d_in[21];
    const float* bm3  = (const float*)d_in[22];
    const float* lng  = (const float*)d_in[23];
    const float* lnb  = (const float*)d_in[24];
    const float* Wc1  = (const float*)d_in[25];
    const float* bc1  = (const float*)d_in[26];
    const float* Wc2  = (const float*)d_in[27];
    const float* bc2  = (const float*)d_in[28];
    float* out = (float*)d_out;

    float* h    = sym(g_h);
    float* Qt   = sym(g_Qt);
    float* Kt   = sym(g_Kt);
    float* Q    = sym(g_Q);
    float* K    = sym(g_K);
    float* V    = sym(g_V);
    float* S    = sym(g_S);
    float* gatt = sym(g_gatt);
    float* mq   = sym(g_mq);
    float* mk   = sym(g_mk);
    float* mv   = sym(g_mv);
    float* mo   = sym(g_mo);
    float* mha  = sym(g_mha);
    float* eA   = sym(g_eA);
    float* eB   = sym(g_eB);
    float* m1   = sym(g_m1);
    float* m2   = sym(g_m2);
    float* agg  = sym(g_agg);
    float* pool = sym(g_pool);
    float* z    = sym(g_z);
    unsigned* mask = (unsigned*)sym(g_mask);

    const int TPB = 256;

    // adjacency mask
    zero_u32_k<<<(NN * MW + TPB - 1) / TPB, TPB>>>(mask, NN * MW);
    build_mask_k<<<(EE + TPB - 1) / TPB, TPB>>>(ei, mask);

    // h = relu(x @ Wi + bi)
    gemm(x, IND, Wi, HDIM, h, HDIM, NN, HDIM, IND, bi, 1, false);

    for (int l = 0; l < LL; l++) {
        const float* Wq_l  = Wq  + (size_t)l * HDIM * QD;
        const float* Wk_l  = Wk  + (size_t)l * HDIM * QD;
        const float* Wv_l  = Wv  + (size_t)l * HDIM * QD;
        const float* Bc_l  = Bc  + (size_t)l * QD * QD;
        const float* ce_l  = cemb + (size_t)l * 50 * QD;
        const float* Win_l = Win + (size_t)l * QD * 3 * QD;
        const float* bin_l = binp + (size_t)l * 3 * QD;
        const float* Wo_l  = Wo  + (size_t)l * QD * QD;
        const float* Wm1_l = Wm1 + (size_t)l * (2 * HDIM + QD) * QD;
        const float* Wm2_l = Wm2 + (size_t)l * QD * QD;
        const float* Wm3_l = Wm3 + (size_t)l * QD * HDIM;

        // Q/K/V projections
        gemm(h, HDIM, Wq_l, QD, Qt, QD, NN, QD, HDIM, bq + l * QD, 0, false);
        gemm(h, HDIM, Wk_l, QD, Kt, QD, NN, QD, HDIM, bk + l * QD, 0, false);
        gemm(h, HDIM, Wv_l, QD, V,  QD, NN, QD, HDIM, bv + l * QD, 0, false);
        // biological constraint: Q = Qt@Bc, K = Kt@Bc^T
        gemm(Qt, QD, Bc_l, QD, Q, QD, NN, QD, QD, nullptr, 0, false);
        gemm(Kt, QD, Bc_l, QD, K, QD, NN, QD, QD, nullptr, 0, true);
        // + 0.1 * cell-type embedding
        add_ce_k<<<(NN * QD + TPB - 1) / TPB, TPB>>>(Q, K, ce_l, ct);

        // graph-masked dense attention
        gemm(Q, QD, K, QD, S, NN, NN, NN, QD, nullptr, 0, true);
        masked_softmax_k<<<NN, 256>>>(S, mask, 0.0625f);           // 1/sqrt(256)
        gemm(S, NN, V, QD, gatt, QD, NN, QD, NN, nullptr, 0, false);

        // MHA input projections (q from Q, k from K, v from V)
        gemm(Q, QD, Win_l,          3 * QD, mq, QD, NN, QD, QD, bin_l,          0, false);
        gemm(K, QD, Win_l + QD,     3 * QD, mk, QD, NN, QD, QD, bin_l + QD,     0, false);
        gemm(V, QD, Win_l + 2 * QD, 3 * QD, mv, QD, NN, QD, QD, bin_l + 2 * QD, 0, false);

        // per-head attention, reusing S
        for (int hh = 0; hh < NHD; hh++) {
            gemm(mq + hh * HD, QD, mk + hh * HD, QD, S, NN, NN, NN, HD, nullptr, 0, true);
            softmax_k<<<NN, 256>>>(S, 0.17677669529663687f);        // 1/sqrt(32)
            gemm(S, NN, mv + hh * HD, QD, mo + hh * HD, QD, NN, HD, NN, nullptr, 0, false);
        }
        gemm(mo, QD, Wo_l, QD, mha, QD, NN, QD, QD, bo + l * QD, 0, false);

        // edge message MLP (first layer factored through node GEMMs)
        gemm(h, HDIM, Wm1_l,              QD, eA, QD, NN, QD, HDIM, nullptr, 0, false); // tgt part
        gemm(h, HDIM, Wm1_l + HDIM * QD,  QD, eB, QD, NN, QD, HDIM, nullptr, 0, false); // src part
        edge_m1_k<<<(EE * QD + TPB - 1) / TPB, TPB>>>(eA, eB, ei, bm1 + l * QD, m1);
        gemm(m1, QD, Wm2_l, QD, m2, QD, EE, QD, QD, bm2 + l * QD, 1, false);
        gemm(m2, QD, Wm3_l, HDIM, m1, HDIM, EE, HDIM, QD, bm3 + l * HDIM, 0, false); // m3 -> m1
        zero_f32_k<<<(NN * HDIM + TPB - 1) / TPB, TPB>>>(agg, NN * HDIM);
        scatter_k<<<(EE * QD + TPB - 1) / TPB, TPB>>>(m1, ei, agg);

        // residual + aggregate + LN
        combine_ln_k<<<NN, HDIM>>>(h, agg, mha, gatt, lng + l * HDIM, lnb + l * HDIM);
    }

    // readout
    pool_k<<<2 * HDIM, 256>>>(h, pool);
    fc1_k<<<HDIM, 256>>>(pool, Wc1, bc1, z);
    fc2_k<<<OUTD, 256>>>(z, Wc2, bc2, out);
}

// round 3
// speedup vs baseline: 1.9819x; 1.9819x over previous
#include <cuda_runtime.h>
#include <math.h>

// ---------------- problem constants ----------------
#define NN   4096
#define EE   65536
#define IND  512
#define HDIM 256
#define QD   256
#define NHD  8
#define HD   32
#define OUTD 10
#define LL   2
#define MW   (NN/32)   // mask words per row

// ---------------- static scratch (device globals; no runtime alloc) ----------------
__device__ float    g_h   [NN*HDIM];
__device__ float    g_Qt  [NN*QD];
__device__ float    g_Kt  [NN*QD];
__device__ float    g_Q   [NN*QD];
__device__ float    g_K   [NN*QD];
__device__ float    g_V   [NN*QD];
__device__ float    g_S   [(size_t)NN*NN];          // graph scores (64MB)
__device__ float    g_Sh  [(size_t)NHD*NN*NN];      // per-head scores (512MB)
__device__ float    g_rs  [NN];                     // graph softmax inv-sums
__device__ float    g_rsh [NHD*NN];                 // head softmax inv-sums
__device__ float    g_gatt[NN*QD];
__device__ float    g_mq  [NN*QD];
__device__ float    g_mk  [NN*QD];
__device__ float    g_mv  [NN*QD];
__device__ float    g_mo  [NN*QD];
__device__ float    g_mha [NN*QD];
__device__ float    g_eA  [NN*QD];
__device__ float    g_eB  [NN*QD];
__device__ float    g_m1  [(size_t)EE*QD];          // 64MB (also reused for m3)
__device__ float    g_m2  [(size_t)EE*QD];          // 64MB
__device__ unsigned g_mask[(size_t)NN*MW];
__device__ float    g_agg [NN*HDIM];
__device__ float    g_pool[2*HDIM];
__device__ float    g_z   [HDIM];

// =====================================================================
// Fast tiled SGEMM.
//  C[M,N] = act( A[M,K] * op(B) + bias ) * rowScale
//  op(B)=B[K,N] (TRANSB=0) or B^T with B stored [N,K] (TRANSB=1)
//  blockIdx.z: batch index (SPLITK==1) or K-split index (SPLITK>1, atomic output)
//  Requirements (enforced by caller): M%BM==0, N%BN==0, K%16==0, strides %4==0,
//  pointers 16B-aligned.
// =====================================================================
template<int BM, int BN, int TM, int TN, int TRANSB, int SPLITK>
__global__ __launch_bounds__(256, 2)
void fgemm_k(const float* __restrict__ A, int lda, long long sA,
             const float* __restrict__ B, int ldb, long long sB,
             float* __restrict__ C, int ldc, long long sC,
             int K,
             const float* __restrict__ bias, int act,
             const float* __restrict__ rowScale, long long sRS)
{
    constexpr int BK  = 16;
    constexpr int TX  = BN / TN;
    constexpr int TY  = BM / TM;
    constexpr int NT  = TX * TY;                 // 256
    constexpr int AL4 = (BM * BK / 4) / NT;      // float4 loads of A per thread
    constexpr int BT4 = BK * BN / 4;             // total float4 in B tile
    constexpr int BL4 = (BT4 + NT - 1) / NT;

    const int tid = threadIdx.x;
    const int tx  = tid % TX;
    const int ty  = tid / TX;
    const int m0  = blockIdx.y * BM;
    const int n0  = blockIdx.x * BN;

    const float* Ab;
    const float* Bb;
    float*       Cb;
    const float* rsb;
    int kbeg, kend;
    if (SPLITK > 1) {
        Ab = A; Bb = B; Cb = C; rsb = rowScale;
        int kc = K / SPLITK;
        kbeg = blockIdx.z * kc;
        kend = kbeg + kc;
    } else {
        Ab  = A + sA * blockIdx.z;
        Bb  = B + sB * blockIdx.z;
        Cb  = C + sC * blockIdx.z;
        rsb = rowScale ? rowScale + sRS * blockIdx.z : nullptr;
        kbeg = 0; kend = K;
    }

    __shared__ float As[BK][BM + 4];
    __shared__ float Bs[BK][BN + 4];

    float4 pa[AL4], pb[BL4];

    auto loadA = [&](int k0) {
#pragma unroll
        for (int j = 0; j < AL4; j++) {
            int idx = tid + j * NT;
            int am  = idx / (BK / 4);
            int ak4 = idx % (BK / 4);
            pa[j] = *reinterpret_cast<const float4*>(
                &Ab[(size_t)(m0 + am) * lda + k0 + ak4 * 4]);
        }
    };
    auto storeA = [&]() {
#pragma unroll
        for (int j = 0; j < AL4; j++) {
            int idx = tid + j * NT;
            int am  = idx / (BK / 4);
            int ak4 = idx % (BK / 4);
            As[ak4 * 4 + 0][am] = pa[j].x;
            As[ak4 * 4 + 1][am] = pa[j].y;
            As[ak4 * 4 + 2][am] = pa[j].z;
            As[ak4 * 4 + 3][am] = pa[j].w;
        }
    };
    auto loadB = [&](int k0) {
#pragma unroll
        for (int j = 0; j < BL4; j++) {
            int idx = tid + j * NT;
            if (idx < BT4) {
                if (TRANSB) {
                    int bn  = idx / (BK / 4);
                    int bk4 = idx % (BK / 4);
                    pb[j] = *reinterpret_cast<const float4*>(
                        &Bb[(size_t)(n0 + bn) * ldb + k0 + bk4 * 4]);
                } else {
                    int bk  = idx / (BN / 4);
                    int bn4 = idx % (BN / 4);
                    pb[j] = *reinterpret_cast<const float4*>(
                        &Bb[(size_t)(k0 + bk) * ldb + n0 + bn4 * 4]);
                }
            }
        }
    };
    auto storeB = [&]() {
#pragma unroll
        for (int j = 0; j < BL4; j++) {
            int idx = tid + j * NT;
            if (idx < BT4) {
                if (TRANSB) {
                    int bn  = idx / (BK / 4);
                    int bk4 = idx % (BK / 4);
                    Bs[bk4 * 4 + 0][bn] = pb[j].x;
                    Bs[bk4 * 4 + 1][bn] = pb[j].y;
                    Bs[bk4 * 4 + 2][bn] = pb[j].z;
                    Bs[bk4 * 4 + 3][bn] = pb[j].w;
                } else {
                    int bk  = idx / (BN / 4);
                    int bn4 = idx % (BN / 4);
                    *reinterpret_cast<float4*>(&Bs[bk][bn4 * 4]) = pb[j];
                }
            }
        }
    };

    loadA(kbeg); loadB(kbeg);
    storeA();    storeB();
    __syncthreads();

    float acc[TM][TN];
#pragma unroll
    for (int i = 0; i < TM; i++)
#pragma unroll
        for (int j = 0; j < TN; j++) acc[i][j] = 0.f;

    for (int k0 = kbeg; k0 < kend; k0 += BK) {
        bool more = (k0 + BK) < kend;
        if (more) { loadA(k0 + BK); loadB(k0 + BK); }

#pragma unroll
        for (int kk = 0; kk < BK; kk++) {
            float ra[TM], rb[TN];
            if constexpr (TM % 4 == 0) {
#pragma unroll
                for (int i = 0; i < TM / 4; i++)
                    *reinterpret_cast<float4*>(&ra[i * 4]) =
                        *reinterpret_cast<const float4*>(&As[kk][ty * TM + i * 4]);
            } else {
#pragma unroll
                for (int i = 0; i < TM; i++) ra[i] = As[kk][ty * TM + i];
            }
            if constexpr (TN % 4 == 0) {
#pragma unroll
                for (int j = 0; j < TN / 4; j++)
                    *reinterpret_cast<float4*>(&rb[j * 4]) =
                        *reinterpret_cast<const float4*>(&Bs[kk][tx * TN + j * 4]);
            } else {
#pragma unroll
                for (int j = 0; j < TN; j++) rb[j] = Bs[kk][tx * TN + j];
            }
#pragma unroll
            for (int i = 0; i < TM; i++)
#pragma unroll
                for (int j = 0; j < TN; j++)
                    acc[i][j] = fmaf(ra[i], rb[j], acc[i][j]);
        }
        __syncthreads();
        if (more) { storeA(); storeB(); __syncthreads(); }
    }

#pragma unroll
    for (int i = 0; i < TM; i++) {
        int gm = m0 + ty * TM + i;
        float rsv = rsb ? rsb[gm] : 1.f;
#pragma unroll
        for (int j = 0; j < TN; j++) {
            int gn = n0 + tx * TN + j;
            float v = acc[i][j];
            if (bias) v += bias[gn];
            v *= rsv;
            if (act == 1) v = fmaxf(v, 0.f);
            if (SPLITK > 1) atomicAdd(&Cb[(size_t)gm * ldc + gn], v);
            else            Cb[(size_t)gm * ldc + gn] = v;
        }
    }
}

// ---------------- block reductions (256 threads) ----------------
__device__ __forceinline__ float blkMax(float v) {
    __shared__ float sh[8];
#pragma unroll
    for (int o = 16; o; o >>= 1) v = fmaxf(v, __shfl_xor_sync(0xffffffffu, v, o));
    if ((threadIdx.x & 31) == 0) sh[threadIdx.x >> 5] = v;
    __syncthreads();
    if (threadIdx.x < 32) {
        float w = (threadIdx.x < 8) ? sh[threadIdx.x] : -3.4e38f;
#pragma unroll
        for (int o = 4; o; o >>= 1) w = fmaxf(w, __shfl_xor_sync(0xffffffffu, w, o));
        if (threadIdx.x == 0) sh[0] = w;
    }
    __syncthreads();
    float r = sh[0];
    __syncthreads();
    return r;
}
__device__ __forceinline__ float blkSum(float v) {
    __shared__ float sh[8];
#pragma unroll
    for (int o = 16; o; o >>= 1) v += __shfl_xor_sync(0xffffffffu, v, o);
    if ((threadIdx.x & 31) == 0) sh[threadIdx.x >> 5] = v;
    __syncthreads();
    if (threadIdx.x < 32) {
        float w = (threadIdx.x < 8) ? sh[threadIdx.x] : 0.f;
#pragma unroll
        for (int o = 4; o; o >>= 1) w += __shfl_xor_sync(0xffffffffu, w, o);
        if (threadIdx.x == 0) sh[0] = w;
    }
    __syncthreads();
    float r = sh[0];
    __syncthreads();
    return r;
}

// ---------------- elementwise / reduction kernels ----------------
__global__ void zero_u32_k(unsigned* __restrict__ p, int n) {
    int i = blockIdx.x * blockDim.x + threadIdx.x;
    if (i < n) p[i] = 0u;
}
__global__ void zero_f32_k(float* __restrict__ p, int n) {
    int i = blockIdx.x * blockDim.x + threadIdx.x;
    if (i < n) p[i] = 0.f;
}
__global__ void build_mask_k(const int* __restrict__ ei, unsigned* __restrict__ mask) {
    int e = blockIdx.x * blockDim.x + threadIdx.x;
    if (e >= EE) return;
    int s = ei[e], t = ei[EE + e];
    atomicOr(&mask[(size_t)s * MW + (t >> 5)], 1u << (t & 31));
}
__global__ void add_ce_k(float4* __restrict__ Q, float4* __restrict__ K,
                         const float4* __restrict__ ce, const int* __restrict__ ct) {
    int idx = blockIdx.x * blockDim.x + threadIdx.x;       // NN*64
    if (idx >= NN * (QD / 4)) return;
    int i = idx >> 6, j4 = idx & 63;
    float4 c = ce[ct[i] * (QD / 4) + j4];
    float4 q = Q[idx], k = K[idx];
    q.x += 0.1f * c.x; q.y += 0.1f * c.y; q.z += 0.1f * c.z; q.w += 0.1f * c.w;
    k.x += 0.1f * c.x; k.y += 0.1f * c.y; k.z += 0.1f * c.z; k.w += 0.1f * c.w;
    Q[idx] = q; K[idx] = k;
}

// graph-masked softmax: writes UNNORMALIZED exp, inv-sum to rs[r]
__global__ void masked_softmax_k(float* __restrict__ S, const unsigned* __restrict__ mask,
                                 float* __restrict__ rs, float scale) {
    int r = blockIdx.x, t = threadIdx.x;
    const unsigned* mrow = mask + (size_t)r * MW;
    float4* row = reinterpret_cast<float4*>(S + (size_t)r * NN);

    float mx = -3.4e38f;
    for (int c4 = t; c4 < NN / 4; c4 += 256) {
        float4 v = row[c4];
        unsigned w = mrow[c4 >> 3];
        int off = (c4 & 7) * 4;
        float a0 = ((w >> (off + 0)) & 1u) ? v.x * scale : -1e9f;
        float a1 = ((w >> (off + 1)) & 1u) ? v.y * scale : -1e9f;
        float a2 = ((w >> (off + 2)) & 1u) ? v.z * scale : -1e9f;
        float a3 = ((w >> (off + 3)) & 1u) ? v.w * scale : -1e9f;
        mx = fmaxf(mx, fmaxf(fmaxf(a0, a1), fmaxf(a2, a3)));
    }
    mx = blkMax(mx);

    float sum = 0.f;
    for (int c4 = t; c4 < NN / 4; c4 += 256) {
        float4 v = row[c4];
        unsigned w = mrow[c4 >> 3];
        int off = (c4 & 7) * 4;
        float a0 = ((w >> (off + 0)) & 1u) ? v.x * scale : -1e9f;
        float a1 = ((w >> (off + 1)) & 1u) ? v.y * scale : -1e9f;
        float a2 = ((w >> (off + 2)) & 1u) ? v.z * scale : -1e9f;
        float a3 = ((w >> (off + 3)) & 1u) ? v.w * scale : -1e9f;
        float4 e;
        e.x = __expf(a0 - mx); e.y = __expf(a1 - mx);
        e.z = __expf(a2 - mx); e.w = __expf(a3 - mx);
        sum += e.x + e.y + e.z + e.w;
        row[c4] = e;
    }
    sum = blkSum(sum);
    if (t == 0) rs[r] = 1.f / sum;
}

// batched per-head softmax: blockIdx.x=row, blockIdx.y=head
__global__ void softmax_h_k(float* __restrict__ Sh, float* __restrict__ rsh, float scale) {
    int r = blockIdx.x, hh = blockIdx.y, t = threadIdx.x;
    float4* row = reinterpret_cast<float4*>(Sh + (size_t)hh * NN * NN + (size_t)r * NN);

    float mx = -3.4e38f;
    for (int c4 = t; c4 < NN / 4; c4 += 256) {
        float4 v = row[c4];
        mx = fmaxf(mx, fmaxf(fmaxf(v.x, v.y), fmaxf(v.z, v.w)));
    }
    mx = blkMax(mx) * scale;

    float sum = 0.f;
    for (int c4 = t; c4 < NN / 4; c4 += 256) {
        float4 v = row[c4];
        float4 e;
        e.x = __expf(v.x * scale - mx); e.y = __expf(v.y * scale - mx);
        e.z = __expf(v.z * scale - mx); e.w = __expf(v.w * scale - mx);
        sum += e.x + e.y + e.z + e.w;
        row[c4] = e;
    }
    sum = blkSum(sum);
    if (t == 0) rsh[hh * NN + r] = 1.f / sum;
}

// m1[e] = relu(eA[tgt[e]] + eB[src[e]] + bm1)   (float4)
__global__ void edge_m1_k(const float4* __restrict__ eA, const float4* __restrict__ eB,
                          const int* __restrict__ ei, const float4* __restrict__ bm1,
                          float4* __restrict__ m1) {
    int idx = blockIdx.x * blockDim.x + threadIdx.x;       // EE*64
    if (idx >= EE * (QD / 4)) return;
    int e = idx >> 6, j4 = idx & 63;
    int t = ei[EE + e], s = ei[e];
    float4 a = eA[t * (QD / 4) + j4];
    float4 b = eB[s * (QD / 4) + j4];
    float4 c = bm1[j4];
    float4 r;
    r.x = fmaxf(a.x + b.x + c.x, 0.f);
    r.y = fmaxf(a.y + b.y + c.y, 0.f);
    r.z = fmaxf(a.z + b.z + c.z, 0.f);
    r.w = fmaxf(a.w + b.w + c.w, 0.f);
    m1[idx] = r;
}

__global__ void scatter_k(const float4* __restrict__ m3, const int* __restrict__ ei,
                          float* __restrict__ agg) {
    int idx = blockIdx.x * blockDim.x + threadIdx.x;       // EE*64
    if (idx >= EE * (HDIM / 4)) return;
    int e = idx >> 6, j4 = idx & 63;
    float4 v = m3[idx];
    float* dst = agg + (size_t)ei[EE + e] * HDIM + j4 * 4;
    atomicAdd(dst + 0, v.x);
    atomicAdd(dst + 1, v.y);
    atomicAdd(dst + 2, v.z);
    atomicAdd(dst + 3, v.w);
}

// h = LN(res + agg + mha + gatt) * g + b
__global__ void combine_ln_k(float* __restrict__ h, const float* __restrict__ agg,
                             const float* __restrict__ mha, const float* __restrict__ gatt,
                             const float* __restrict__ g, const float* __restrict__ b) {
    int r = blockIdx.x, j = threadIdx.x;
    size_t idx = (size_t)r * HDIM + j;
    float v = h[idx] + agg[idx] + mha[idx] + gatt[idx];
    float mu = blkSum(v) * (1.f / HDIM);
    float d = v - mu;
    float var = blkSum(d * d) * (1.f / HDIM);
    h[idx] = d * rsqrtf(var + 1e-5f) * g[j] + b[j];
}

// pooled = concat(mean(h,0), max(h,0))
__global__ void pool_k(const float* __restrict__ h, float* __restrict__ pool) {
    int c = blockIdx.x, t = threadIdx.x;
    if (c < HDIM) {
        float s = 0.f;
        for (int r = t; r < NN; r += 256) s += h[(size_t)r * HDIM + c];
        s = blkSum(s);
        if (t == 0) pool[c] = s * (1.f / NN);
    } else {
        int cc = c - HDIM;
        float m = -3.4e38f;
        for (int r = t; r < NN; r += 256) m = fmaxf(m, h[(size_t)r * HDIM + cc]);
        m = blkMax(m);
        if (t == 0) pool[c] = m;
    }
}

__global__ void fc1_k(const float* __restrict__ pool, const float* __restrict__ W,
                      const float* __restrict__ b, float* __restrict__ z) {
    int o = blockIdx.x, t = threadIdx.x;
    float s = 0.f;
    for (int i = t; i < 2 * HDIM; i += 256) s += pool[i] * W[(size_t)i * HDIM + o];
    s = blkSum(s);
    if (t == 0) z[o] = fmaxf(s + b[o], 0.f);
}

__global__ void fc2_k(const float* __restrict__ z, const float* __restrict__ W,
                      const float* __restrict__ b, float* __restrict__ out) {
    int o = blockIdx.x, t = threadIdx.x;
    float s = 0.f;
    for (int i = t; i < HDIM; i += 256) s += z[i] * W[(size_t)i * OUTD + o];
    s = blkSum(s);
    if (t == 0) out[o] = s + b[o];
}

// ---------------- host side ----------------
static float* sym(const void* s) {
    void* p = nullptr;
    cudaGetSymbolAddress(&p, (const void*)s);
    return (float*)p;
}

extern "C" void kernel_launch(void* const* d_in, const int* in_sizes, int n_in,
                              void* d_out, int out_size) {
    const float* x    = (const float*)d_in[0];
    const int*   ei   = (const int*)  d_in[1];
    const int*   ct   = (const int*)  d_in[2];
    const float* Wi   = (const float*)d_in[3];
    const float* bi   = (const float*)d_in[4];
    const float* Wq   = (const float*)d_in[5];
    const float* bq   = (const float*)d_in[6];
    const float* Wk   = (const float*)d_in[7];
    const float* bk   = (const float*)d_in[8];
    const float* Wv   = (const float*)d_in[9];
    const float* bv   = (const float*)d_in[10];
    const float* Bc   = (const float*)d_in[11];
    const float* cemb = (const float*)d_in[12];
    const float* Win  = (const float*)d_in[13];
    const float* binp = (const float*)d_in[14];
    const float* Wo   = (const float*)d_in[15];
    const float* bo   = (const float*)d_in[16];
    const float* Wm1  = (const float*)d_in[17];
    const float* bm1  = (const float*)d_in[18];
    const float* Wm2  = (const float*)d_in[19];
    const float* bm2  = (const float*)d_in[20];
    const float* Wm3  = (const float*)d_in[21];
    const float* bm3  = (const float*)d_in[22];
    const float* lng  = (const float*)d_in[23];
    const float* lnb  = (const float*)d_in[24];
    const float* Wc1  = (const float*)d_in[25];
    const float* bc1  = (const float*)d_in[26];
    const float* Wc2  = (const float*)d_in[27];
    const float* bc2  = (const float*)d_in[28];
    float* out = (float*)d_out;

    float* h    = sym(g_h);
    float* Qt   = sym(g_Qt);
    float* Kt   = sym(g_Kt);
    float* Q    = sym(g_Q);
    float* K    = sym(g_K);
    float* V    = sym(g_V);
    float* S    = sym(g_S);
    float* Sh   = sym(g_Sh);
    float* rs   = sym(g_rs);
    float* rsh  = sym(g_rsh);
    float* gatt = sym(g_gatt);
    float* mq   = sym(g_mq);
    float* mk   = sym(g_mk);
    float* mv   = sym(g_mv);
    float* mo   = sym(g_mo);
    float* mha  = sym(g_mha);
    float* eA   = sym(g_eA);
    float* eB   = sym(g_eB);
    float* m1   = sym(g_m1);
    float* m2   = sym(g_m2);
    float* agg  = sym(g_agg);
    float* pool = sym(g_pool);
    float* z    = sym(g_z);
    unsigned* mask = (unsigned*)sym(g_mask);

    const int TPB = 256;
    const long long SNN = (long long)NN * NN;

    // adjacency mask
    zero_u32_k<<<(NN * MW + TPB - 1) / TPB, TPB>>>(mask, NN * MW);
    build_mask_k<<<(EE + TPB - 1) / TPB, TPB>>>(ei, mask);

    // h = relu(x @ Wi + bi)
    fgemm_k<128,128,8,8,0,1><<<dim3(HDIM/128, NN/128, 1), 256>>>(
        x, IND, 0, Wi, HDIM, 0, h, HDIM, 0, IND, bi, 1, nullptr, 0);

    for (int l = 0; l < LL; l++) {
        const float* Wq_l  = Wq  + (size_t)l * HDIM * QD;
        const float* Wk_l  = Wk  + (size_t)l * HDIM * QD;
        const float* Wv_l  = Wv  + (size_t)l * HDIM * QD;
        const float* Bc_l  = Bc  + (size_t)l * QD * QD;
        const float* ce_l  = cemb + (size_t)l * 50 * QD;
        const float* Win_l = Win + (size_t)l * QD * 3 * QD;
        const float* bin_l = binp + (size_t)l * 3 * QD;
        const float* Wo_l  = Wo  + (size_t)l * QD * QD;
        const float* Wm1_l = Wm1 + (size_t)l * (2 * HDIM + QD) * QD;
        const float* Wm2_l = Wm2 + (size_t)l * QD * QD;
        const float* Wm3_l = Wm3 + (size_t)l * QD * HDIM;

        dim3 gNode(QD/128, NN/128, 1);

        // Q/K/V projections
        fgemm_k<128,128,8,8,0,1><<<gNode, 256>>>(h, HDIM, 0, Wq_l, QD, 0, Qt, QD, 0,
                                                 HDIM, bq + l * QD, 0, nullptr, 0);
        fgemm_k<128,128,8,8,0,1><<<gNode, 256>>>(h, HDIM, 0, Wk_l, QD, 0, Kt, QD, 0,
                                                 HDIM, bk + l * QD, 0, nullptr, 0);
        fgemm_k<128,128,8,8,0,1><<<gNode, 256>>>(h, HDIM, 0, Wv_l, QD, 0, V, QD, 0,
                                                 HDIM, bv + l * QD, 0, nullptr, 0);
        // biological constraint: Q = Qt@Bc, K = Kt@Bc^T
        fgemm_k<128,128,8,8,0,1><<<gNode, 256>>>(Qt, QD, 0, Bc_l, QD, 0, Q, QD, 0,
                                                 QD, nullptr, 0, nullptr, 0);
        fgemm_k<128,128,8,8,1,1><<<gNode, 256>>>(Kt, QD, 0, Bc_l, QD, 0, K, QD, 0,
                                                 QD, nullptr, 0, nullptr, 0);
        add_ce_k<<<(NN * QD / 4 + TPB - 1) / TPB, TPB>>>((float4*)Q, (float4*)K,
                                                         (const float4*)ce_l, ct);

        // graph-masked dense attention
        fgemm_k<128,128,8,8,1,1><<<dim3(NN/128, NN/128, 1), 256>>>(
            Q, QD, 0, K, QD, 0, S, NN, 0, QD, nullptr, 0, nullptr, 0);
        masked_softmax_k<<<NN, 256>>>(S, mask, rs, 0.0625f);          // 1/sqrt(256)
        zero_f32_k<<<(NN * QD + TPB - 1) / TPB, TPB>>>(gatt, NN * QD);
        fgemm_k<128,128,8,8,0,4><<<dim3(QD/128, NN/128, 4), 256>>>(
            S, NN, 0, V, QD, 0, gatt, QD, 0, NN, nullptr, 0, rs, 0);

        // MHA input projections
        fgemm_k<128,128,8,8,0,1><<<gNode, 256>>>(Q, QD, 0, Win_l, 3*QD, 0, mq, QD, 0,
                                                 QD, bin_l, 0, nullptr, 0);
        fgemm_k<128,128,8,8,0,1><<<gNode, 256>>>(K, QD, 0, Win_l + QD, 3*QD, 0, mk, QD, 0,
                                                 QD, bin_l + QD, 0, nullptr, 0);
        fgemm_k<128,128,8,8,0,1><<<gNode, 256>>>(V, QD, 0, Win_l + 2*QD, 3*QD, 0, mv, QD, 0,
                                                 QD, bin_l + 2*QD, 0, nullptr, 0);

        // batched per-head scores: Sh[h] = mq_h @ mk_h^T
        fgemm_k<128,128,8,8,1,1><<<dim3(NN/128, NN/128, NHD), 256>>>(
            mq, QD, HD, mk, QD, HD, Sh, NN, SNN, HD, nullptr, 0, nullptr, 0);
        softmax_h_k<<<dim3(NN, NHD), 256>>>(Sh, rsh, 0.17677669529663687f); // 1/sqrt(32)
        // batched per-head attn@V (output rows scaled by inv-sums)
        fgemm_k<128,32,8,2,0,1><<<dim3(1, NN/128, NHD), 256>>>(
            Sh, NN, SNN, mv, QD, HD, mo, QD, HD, NN, nullptr, 0, rsh, NN);

        fgemm_k<128,128,8,8,0,1><<<gNode, 256>>>(mo, QD, 0, Wo_l, QD, 0, mha, QD, 0,
                                                 QD, bo + l * QD, 0, nullptr, 0);

        // edge message MLP (first layer factored through node GEMMs)
        fgemm_k<128,128,8,8,0,1><<<gNode, 256>>>(h, HDIM, 0, Wm1_l, QD, 0, eA, QD, 0,
                                                 HDIM, nullptr, 0, nullptr, 0);
        fgemm_k<128,128,8,8,0,1><<<gNode, 256>>>(h, HDIM, 0, Wm1_l + HDIM * QD, QD, 0,
                                                 eB, QD, 0, HDIM, nullptr, 0, nullptr, 0);
        edge_m1_k<<<(EE * QD / 4 + TPB - 1) / TPB, TPB>>>(
            (const float4*)eA, (const float4*)eB, ei, (const float4*)(bm1 + l * QD),
            (float4*)m1);
        fgemm_k<128,128,8,8,0,1><<<dim3(QD/128, EE/128, 1), 256>>>(
            m1, QD, 0, Wm2_l, QD, 0, m2, QD, 0, QD, bm2 + l * QD, 1, nullptr, 0);
        fgemm_k<128,128,8,8,0,1><<<dim3(HDIM/128, EE/128, 1), 256>>>(
            m2, QD, 0, Wm3_l, HDIM, 0, m1, HDIM, 0, QD, bm3 + l * HDIM, 0, nullptr, 0);
        zero_f32_k<<<(NN * HDIM + TPB - 1) / TPB, TPB>>>(agg, NN * HDIM);
        scatter_k<<<(EE * HDIM / 4 + TPB - 1) / TPB, TPB>>>((const float4*)m1, ei, agg);

        // residual + aggregate + LN
        combine_ln_k<<<NN, HDIM>>>(h, agg, mha, gatt, lng + l * HDIM, lnb + l * HDIM);
    }

    // readout
    pool_k<<<2 * HDIM, 256>>>(h, pool);
    fc1_k<<<HDIM, 256>>>(pool, Wc1, bc1, z);
    fc2_k<<<OUTD, 256>>>(z, Wc2, bc2, out);
}

// round 4
// speedup vs baseline: 3.8352x; 1.9351x over previous
#include <cuda_runtime.h>
#include <math.h>

// ---------------- problem constants ----------------
#define NN   4096
#define EE   65536
#define IND  512
#define HDIM 256
#define QD   256
#define NHD  8
#define HD   32
#define OUTD 10
#define LL   2
#define MW   (NN/32)   // mask words per row

// ---------------- static scratch (device globals; no runtime alloc) ----------------
__device__ float    g_h   [NN*HDIM];
__device__ float    g_Qt  [NN*QD];
__device__ float    g_Kt  [NN*QD];
__device__ float    g_Q   [NN*QD];
__device__ float    g_K   [NN*QD];
__device__ float    g_V   [NN*QD];
__device__ float    g_S   [(size_t)NN*NN];          // graph scores (64MB)
__device__ float    g_Sh  [(size_t)NHD*NN*NN];      // per-head scores (512MB)
__device__ float    g_rs  [NN];                     // graph softmax inv-sums
__device__ float    g_rsh [NHD*NN];                 // head softmax inv-sums
__device__ float    g_gatt[NN*QD];
__device__ float    g_mq  [NN*QD];
__device__ float    g_mk  [NN*QD];
__device__ float    g_mv  [NN*QD];
__device__ float    g_mo  [NN*QD];
__device__ float    g_mha [NN*QD];
__device__ float    g_eA  [NN*QD];
__device__ float    g_eB  [NN*QD];
__device__ float    g_m1  [(size_t)EE*QD];          // 64MB (also reused for m3)
__device__ float    g_m2  [(size_t)EE*QD];          // 64MB
__device__ unsigned g_mask[(size_t)NN*MW];
__device__ float    g_agg [NN*HDIM];
__device__ float    g_pool[2*HDIM];
__device__ float    g_z   [HDIM];

// =====================================================================
// TF32 tensor-core GEMM (mma.sync.m16n8k8, fp32 accumulate).
//  C[M,N] = act( A[M,K] * op(B) + bias ) * rowScale
//  op(B)=B[K,N] (TRANSB=0) or B^T with B stored [N,K] (TRANSB=1)
//  blockIdx.z: batch index (SPLITK==1) or K-split index (SPLITK>1, atomic C,
//  caller must pre-zero C and pass bias=nullptr, act=0).
//  Caller guarantees: M%BM==0, N%BN==0, K%32==0, pointers/ld 16B-aligned.
// =====================================================================
__device__ __forceinline__ unsigned f2tf(float f) {
    unsigned u;
    asm("cvt.rna.tf32.f32 %0, %1;" : "=r"(u) : "f"(f));
    return u;
}
__device__ __forceinline__ uint4 f2tf4(float4 v) {
    uint4 u;
    u.x = f2tf(v.x); u.y = f2tf(v.y); u.z = f2tf(v.z); u.w = f2tf(v.w);
    return u;
}
__device__ __forceinline__ void mma_tf32(float* c, const unsigned* a, const unsigned* b) {
    asm volatile(
        "mma.sync.aligned.m16n8k8.row.col.f32.tf32.tf32.f32 "
        "{%0,%1,%2,%3}, {%4,%5,%6,%7}, {%8,%9}, {%0,%1,%2,%3};"
        : "+f"(c[0]), "+f"(c[1]), "+f"(c[2]), "+f"(c[3])
        : "r"(a[0]), "r"(a[1]), "r"(a[2]), "r"(a[3]), "r"(b[0]), "r"(b[1]));
}

template<int BM, int BN, int WM, int WN, int TRANSB, int SPLITK>
__global__ __launch_bounds__(256)
void tgemm_k(const float* __restrict__ A, int lda, long long sA,
             const float* __restrict__ B, int ldb, long long sB,
             float* __restrict__ C, int ldc, long long sC,
             int K,
             const float* __restrict__ bias, int act,
             const float* __restrict__ rowScale, long long sRS)
{
    constexpr int BK  = 32;
    constexpr int PAD = 4;
    constexpr int WX  = BN / WN;          // warps along N
    constexpr int WY  = BM / WM;          // warps along M
    static_assert(WX * WY == 8, "8 warps");
    constexpr int MM  = WM / 16;          // mma tiles per warp (M)
    constexpr int MN  = WN / 8;           // mma tiles per warp (N)
    constexpr int AL4 = BM * BK / 4 / 256;
    constexpr int BT4 = BK * BN / 4;
    constexpr int BL4 = (BT4 + 255) / 256;

    const int tid  = threadIdx.x;
    const int wid  = tid >> 5;
    const int lane = tid & 31;
    const int wx   = wid % WX;
    const int wy   = wid / WX;
    const int lg   = lane >> 2;           // 0..7
    const int lt   = lane & 3;            // 0..3
    const int m0   = blockIdx.y * BM;
    const int n0   = blockIdx.x * BN;

    const float* Ab;
    const float* Bb;
    float*       Cb;
    const float* rsb;
    int kbeg, kend;
    if (SPLITK > 1) {
        Ab = A; Bb = B; Cb = C; rsb = rowScale;
        int kc = K / SPLITK;
        kbeg = blockIdx.z * kc;
        kend = kbeg + kc;
    } else {
        Ab  = A + sA * blockIdx.z;
        Bb  = B + sB * blockIdx.z;
        Cb  = C + sC * blockIdx.z;
        rsb = rowScale ? rowScale + sRS * blockIdx.z : nullptr;
        kbeg = 0; kend = K;
    }

    __shared__ unsigned As[BM][BK + PAD];   // [m][k]
    __shared__ unsigned Bs[BK][BN + PAD];   // [k][n]

    uint4 pa[AL4], pb[BL4];

    auto loadA = [&](int k0) {
#pragma unroll
        for (int j = 0; j < AL4; j++) {
            int idx = tid + j * 256;
            int m   = idx >> 3;           // BK/4 = 8 float4 per row
            int k4  = idx & 7;
            pa[j] = f2tf4(*reinterpret_cast<const float4*>(
                &Ab[(size_t)(m0 + m) * lda + k0 + k4 * 4]));
        }
    };
    auto storeA = [&]() {
#pragma unroll
        for (int j = 0; j < AL4; j++) {
            int idx = tid + j * 256;
            int m   = idx >> 3;
            int k4  = idx & 7;
            *reinterpret_cast<uint4*>(&As[m][k4 * 4]) = pa[j];
        }
    };
    auto loadB = [&](int k0) {
#pragma unroll
        for (int j = 0; j < BL4; j++) {
            int idx = tid + j * 256;
            if (idx < BT4) {
                if (TRANSB) {
                    int n  = idx >> 3;
                    int k4 = idx & 7;
                    pb[j] = f2tf4(*reinterpret_cast<const float4*>(
                        &Bb[(size_t)(n0 + n) * ldb + k0 + k4 * 4]));
                } else {
                    int k  = idx / (BN / 4);
                    int n4 = idx % (BN / 4);
                    pb[j] = f2tf4(*reinterpret_cast<const float4*>(
                        &Bb[(size_t)(k0 + k) * ldb + n0 + n4 * 4]));
                }
            }
        }
    };
    auto storeB = [&]() {
#pragma unroll
        for (int j = 0; j < BL4; j++) {
            int idx = tid + j * 256;
            if (idx < BT4) {
                if (TRANSB) {
                    int n  = idx >> 3;
                    int k4 = idx & 7;
                    Bs[k4 * 4 + 0][n] = pb[j].x;
                    Bs[k4 * 4 + 1][n] = pb[j].y;
                    Bs[k4 * 4 + 2][n] = pb[j].z;
                    Bs[k4 * 4 + 3][n] = pb[j].w;
                } else {
                    int k  = idx / (BN / 4);
                    int n4 = idx % (BN / 4);
                    *reinterpret_cast<uint4*>(&Bs[k][n4 * 4]) = pb[j];
                }
            }
        }
    };

    loadA(kbeg); loadB(kbeg);
    storeA();    storeB();
    __syncthreads();

    float acc[MM][MN][4];
#pragma unroll
    for (int i = 0; i < MM; i++)
#pragma unroll
        for (int j = 0; j < MN; j++)
#pragma unroll
            for (int c = 0; c < 4; c++) acc[i][j][c] = 0.f;

    for (int k0 = kbeg; k0 < kend; k0 += BK) {
        bool more = (k0 + BK) < kend;
        if (more) { loadA(k0 + BK); loadB(k0 + BK); }

#pragma unroll
        for (int ks = 0; ks < BK / 8; ks++) {
            const int kk = ks * 8;
            unsigned af[MM][4], bf[MN][2];
#pragma unroll
            for (int i = 0; i < MM; i++) {
                int row = wy * WM + i * 16 + lg;
                af[i][0] = As[row    ][kk + lt    ];
                af[i][1] = As[row + 8][kk + lt    ];
                af[i][2] = As[row    ][kk + lt + 4];
                af[i][3] = As[row + 8][kk + lt + 4];
            }
#pragma unroll
            for (int j = 0; j < MN; j++) {
                int col = wx * WN + j * 8 + lg;
                bf[j][0] = Bs[kk + lt    ][col];
                bf[j][1] = Bs[kk + lt + 4][col];
            }
#pragma unroll
            for (int i = 0; i < MM; i++)
#pragma unroll
                for (int j = 0; j < MN; j++)
                    mma_tf32(acc[i][j], af[i], bf[j]);
        }
        __syncthreads();
        if (more) { storeA(); storeB(); __syncthreads(); }
    }

    // epilogue
#pragma unroll
    for (int i = 0; i < MM; i++) {
        int mA = m0 + wy * WM + i * 16 + lg;
        int mB = mA + 8;
        float rsA = rsb ? rsb[mA] : 1.f;
        float rsB = rsb ? rsb[mB] : 1.f;
#pragma unroll
        for (int j = 0; j < MN; j++) {
            int n = n0 + wx * WN + j * 8 + lt * 2;
            float b0 = bias ? bias[n] : 0.f;
            float b1 = bias ? bias[n + 1] : 0.f;
            float v0 = (acc[i][j][0] + b0) * rsA;
            float v1 = (acc[i][j][1] + b1) * rsA;
            float v2 = (acc[i][j][2] + b0) * rsB;
            float v3 = (acc[i][j][3] + b1) * rsB;
            if (act == 1) {
                v0 = fmaxf(v0, 0.f); v1 = fmaxf(v1, 0.f);
                v2 = fmaxf(v2, 0.f); v3 = fmaxf(v3, 0.f);
            }
            if (SPLITK > 1) {
                atomicAdd(&Cb[(size_t)mA * ldc + n],     v0);
                atomicAdd(&Cb[(size_t)mA * ldc + n + 1], v1);
                atomicAdd(&Cb[(size_t)mB * ldc + n],     v2);
                atomicAdd(&Cb[(size_t)mB * ldc + n + 1], v3);
            } else {
                Cb[(size_t)mA * ldc + n]     = v0;
                Cb[(size_t)mA * ldc + n + 1] = v1;
                Cb[(size_t)mB * ldc + n]     = v2;
                Cb[(size_t)mB * ldc + n + 1] = v3;
            }
        }
    }
}

// ---------------- block reductions (256 threads) ----------------
__device__ __forceinline__ float blkMax(float v) {
    __shared__ float sh[8];
#pragma unroll
    for (int o = 16; o; o >>= 1) v = fmaxf(v, __shfl_xor_sync(0xffffffffu, v, o));
    if ((threadIdx.x & 31) == 0) sh[threadIdx.x >> 5] = v;
    __syncthreads();
    if (threadIdx.x < 32) {
        float w = (threadIdx.x < 8) ? sh[threadIdx.x] : -3.4e38f;
#pragma unroll
        for (int o = 4; o; o >>= 1) w = fmaxf(w, __shfl_xor_sync(0xffffffffu, w, o));
        if (threadIdx.x == 0) sh[0] = w;
    }
    __syncthreads();
    float r = sh[0];
    __syncthreads();
    return r;
}
__device__ __forceinline__ float blkSum(float v) {
    __shared__ float sh[8];
#pragma unroll
    for (int o = 16; o; o >>= 1) v += __shfl_xor_sync(0xffffffffu, v, o);
    if ((threadIdx.x & 31) == 0) sh[threadIdx.x >> 5] = v;
    __syncthreads();
    if (threadIdx.x < 32) {
        float w = (threadIdx.x < 8) ? sh[threadIdx.x] : 0.f;
#pragma unroll
        for (int o = 4; o; o >>= 1) w += __shfl_xor_sync(0xffffffffu, w, o);
        if (threadIdx.x == 0) sh[0] = w;
    }
    __syncthreads();
    float r = sh[0];
    __syncthreads();
    return r;
}

// ---------------- elementwise / reduction kernels ----------------
__global__ void zero_u32_k(unsigned* __restrict__ p, int n) {
    int i = blockIdx.x * blockDim.x + threadIdx.x;
    if (i < n) p[i] = 0u;
}
__global__ void zero_f32_k(float* __restrict__ p, int n) {
    int i = blockIdx.x * blockDim.x + threadIdx.x;
    if (i < n) p[i] = 0.f;
}
__global__ void build_mask_k(const int* __restrict__ ei, unsigned* __restrict__ mask) {
    int e = blockIdx.x * blockDim.x + threadIdx.x;
    if (e >= EE) return;
    int s = ei[e], t = ei[EE + e];
    atomicOr(&mask[(size_t)s * MW + (t >> 5)], 1u << (t & 31));
}
__global__ void add_ce_k(float4* __restrict__ Q, float4* __restrict__ K,
                         const float4* __restrict__ ce, const int* __restrict__ ct) {
    int idx = blockIdx.x * blockDim.x + threadIdx.x;       // NN*64
    if (idx >= NN * (QD / 4)) return;
    int i = idx >> 6, j4 = idx & 63;
    float4 c = ce[ct[i] * (QD / 4) + j4];
    float4 q = Q[idx], k = K[idx];
    q.x += 0.1f * c.x; q.y += 0.1f * c.y; q.z += 0.1f * c.z; q.w += 0.1f * c.w;
    k.x += 0.1f * c.x; k.y += 0.1f * c.y; k.z += 0.1f * c.z; k.w += 0.1f * c.w;
    Q[idx] = q; K[idx] = k;
}

// graph-masked softmax: writes UNNORMALIZED exp, inv-sum to rs[r]
__global__ void masked_softmax_k(float* __restrict__ S, const unsigned* __restrict__ mask,
                                 float* __restrict__ rs, float scale) {
    int r = blockIdx.x, t = threadIdx.x;
    const unsigned* mrow = mask + (size_t)r * MW;
    float4* row = reinterpret_cast<float4*>(S + (size_t)r * NN);

    float mx = -3.4e38f;
    for (int c4 = t; c4 < NN / 4; c4 += 256) {
        float4 v = row[c4];
        unsigned w = mrow[c4 >> 3];
        int off = (c4 & 7) * 4;
        float a0 = ((w >> (off + 0)) & 1u) ? v.x * scale : -1e9f;
        float a1 = ((w >> (off + 1)) & 1u) ? v.y * scale : -1e9f;
        float a2 = ((w >> (off + 2)) & 1u) ? v.z * scale : -1e9f;
        float a3 = ((w >> (off + 3)) & 1u) ? v.w * scale : -1e9f;
        mx = fmaxf(mx, fmaxf(fmaxf(a0, a1), fmaxf(a2, a3)));
    }
    mx = blkMax(mx);

    float sum = 0.f;
    for (int c4 = t; c4 < NN / 4; c4 += 256) {
        float4 v = row[c4];
        unsigned w = mrow[c4 >> 3];
        int off = (c4 & 7) * 4;
        float a0 = ((w >> (off + 0)) & 1u) ? v.x * scale : -1e9f;
        float a1 = ((w >> (off + 1)) & 1u) ? v.y * scale : -1e9f;
        float a2 = ((w >> (off + 2)) & 1u) ? v.z * scale : -1e9f;
        float a3 = ((w >> (off + 3)) & 1u) ? v.w * scale : -1e9f;
        float4 e;
        e.x = __expf(a0 - mx); e.y = __expf(a1 - mx);
        e.z = __expf(a2 - mx); e.w = __expf(a3 - mx);
        sum += e.x + e.y + e.z + e.w;
        row[c4] = e;
    }
    sum = blkSum(sum);
    if (t == 0) rs[r] = 1.f / sum;
}

// batched per-head softmax: blockIdx.x=row, blockIdx.y=head
__global__ void softmax_h_k(float* __restrict__ Sh, float* __restrict__ rsh, float scale) {
    int r = blockIdx.x, hh = blockIdx.y, t = threadIdx.x;
    float4* row = reinterpret_cast<float4*>(Sh + (size_t)hh * NN * NN + (size_t)r * NN);

    float mx = -3.4e38f;
    for (int c4 = t; c4 < NN / 4; c4 += 256) {
        float4 v = row[c4];
        mx = fmaxf(mx, fmaxf(fmaxf(v.x, v.y), fmaxf(v.z, v.w)));
    }
    mx = blkMax(mx) * scale;

    float sum = 0.f;
    for (int c4 = t; c4 < NN / 4; c4 += 256) {
        float4 v = row[c4];
        float4 e;
        e.x = __expf(v.x * scale - mx); e.y = __expf(v.y * scale - mx);
        e.z = __expf(v.z * scale - mx); e.w = __expf(v.w * scale - mx);
        sum += e.x + e.y + e.z + e.w;
        row[c4] = e;
    }
    sum = blkSum(sum);
    if (t == 0) rsh[hh * NN + r] = 1.f / sum;
}

// m1[e] = relu(eA[tgt[e]] + eB[src[e]] + bm1)   (float4)
__global__ void edge_m1_k(const float4* __restrict__ eA, const float4* __restrict__ eB,
                          const int* __restrict__ ei, const float4* __restrict__ bm1,
                          float4* __restrict__ m1) {
    int idx = blockIdx.x * blockDim.x + threadIdx.x;       // EE*64
    if (idx >= EE * (QD / 4)) return;
    int e = idx >> 6, j4 = idx & 63;
    int t = ei[EE + e], s = ei[e];
    float4 a = eA[t * (QD / 4) + j4];
    float4 b = eB[s * (QD / 4) + j4];
    float4 c = bm1[j4];
    float4 r;
    r.x = fmaxf(a.x + b.x + c.x, 0.f);
    r.y = fmaxf(a.y + b.y + c.y, 0.f);
    r.z = fmaxf(a.z + b.z + c.z, 0.f);
    r.w = fmaxf(a.w + b.w + c.w, 0.f);
    m1[idx] = r;
}

__global__ void scatter_k(const float4* __restrict__ m3, const int* __restrict__ ei,
                          float* __restrict__ agg) {
    int idx = blockIdx.x * blockDim.x + threadIdx.x;       // EE*64
    if (idx >= EE * (HDIM / 4)) return;
    int e = idx >> 6, j4 = idx & 63;
    float4 v = m3[idx];
    float* dst = agg + (size_t)ei[EE + e] * HDIM + j4 * 4;
    atomicAdd(dst + 0, v.x);
    atomicAdd(dst + 1, v.y);
    atomicAdd(dst + 2, v.z);
    atomicAdd(dst + 3, v.w);
}

// h = LN(res + agg + mha + gatt) * g + b
__global__ void combine_ln_k(float* __restrict__ h, const float* __restrict__ agg,
                             const float* __restrict__ mha, const float* __restrict__ gatt,
                             const float* __restrict__ g, const float* __restrict__ b) {
    int r = blockIdx.x, j = threadIdx.x;
    size_t idx = (size_t)r * HDIM + j;
    float v = h[idx] + agg[idx] + mha[idx] + gatt[idx];
    float mu = blkSum(v) * (1.f / HDIM);
    float d = v - mu;
    float var = blkSum(d * d) * (1.f / HDIM);
    h[idx] = d * rsqrtf(var + 1e-5f) * g[j] + b[j];
}

// pooled = concat(mean(h,0), max(h,0))
__global__ void pool_k(const float* __restrict__ h, float* __restrict__ pool) {
    int c = blockIdx.x, t = threadIdx.x;
    if (c < HDIM) {
        float s = 0.f;
        for (int r = t; r < NN; r += 256) s += h[(size_t)r * HDIM + c];
        s = blkSum(s);
        if (t == 0) pool[c] = s * (1.f / NN);
    } else {
        int cc = c - HDIM;
        float m = -3.4e38f;
        for (int r = t; r < NN; r += 256) m = fmaxf(m, h[(size_t)r * HDIM + cc]);
        m = blkMax(m);
        if (t == 0) pool[c] = m;
    }
}

__global__ void fc1_k(const float* __restrict__ pool, const float* __restrict__ W,
                      const float* __restrict__ b, float* __restrict__ z) {
    int o = blockIdx.x, t = threadIdx.x;
    float s = 0.f;
    for (int i = t; i < 2 * HDIM; i += 256) s += pool[i] * W[(size_t)i * HDIM + o];
    s = blkSum(s);
    if (t == 0) z[o] = fmaxf(s + b[o], 0.f);
}

__global__ void fc2_k(const float* __restrict__ z, const float* __restrict__ W,
                      const float* __restrict__ b, float* __restrict__ out) {
    int o = blockIdx.x, t = threadIdx.x;
    float s = 0.f;
    for (int i = t; i < HDIM; i += 256) s += z[i] * W[(size_t)i * OUTD + o];
    s = blkSum(s);
    if (t == 0) out[o] = s + b[o];
}

// ---------------- host side ----------------
static float* sym(const void* s) {
    void* p = nullptr;
    cudaGetSymbolAddress(&p, (const void*)s);
    return (float*)p;
}

extern "C" void kernel_launch(void* const* d_in, const int* in_sizes, int n_in,
                              void* d_out, int out_size) {
    const float* x    = (const float*)d_in[0];
    const int*   ei   = (const int*)  d_in[1];
    const int*   ct   = (const int*)  d_in[2];
    const float* Wi   = (const float*)d_in[3];
    const float* bi   = (const float*)d_in[4];
    const float* Wq   = (const float*)d_in[5];
    const float* bq   = (const float*)d_in[6];
    const float* Wk   = (const float*)d_in[7];
    const float* bk   = (const float*)d_in[8];
    const float* Wv   = (const float*)d_in[9];
    const float* bv   = (const float*)d_in[10];
    const float* Bc   = (const float*)d_in[11];
    const float* cemb = (const float*)d_in[12];
    const float* Win  = (const float*)d_in[13];
    const float* binp = (const float*)d_in[14];
    const float* Wo   = (const float*)d_in[15];
    const float* bo   = (const float*)d_in[16];
    const float* Wm1  = (const float*)d_in[17];
    const float* bm1  = (const float*)d_in[18];
    const float* Wm2  = (const float*)d_in[19];
    const float* bm2  = (const float*)d_in[20];
    const float* Wm3  = (const float*)d_in[21];
    const float* bm3  = (const float*)d_in[22];
    const float* lng  = (const float*)d_in[23];
    const float* lnb  = (const float*)d_in[24];
    const float* Wc1  = (const float*)d_in[25];
    const float* bc1  = (const float*)d_in[26];
    const float* Wc2  = (const float*)d_in[27];
    const float* bc2  = (const float*)d_in[28];
    float* out = (float*)d_out;

    float* h    = sym(g_h);
    float* Qt   = sym(g_Qt);
    float* Kt   = sym(g_Kt);
    float* Q    = sym(g_Q);
    float* K    = sym(g_K);
    float* V    = sym(g_V);
    float* S    = sym(g_S);
    float* Sh   = sym(g_Sh);
    float* rs   = sym(g_rs);
    float* rsh  = sym(g_rsh);
    float* gatt = sym(g_gatt);
    float* mq   = sym(g_mq);
    float* mk   = sym(g_mk);
    float* mv   = sym(g_mv);
    float* mo   = sym(g_mo);
    float* mha  = sym(g_mha);
    float* eA   = sym(g_eA);
    float* eB   = sym(g_eB);
    float* m1   = sym(g_m1);
    float* m2   = sym(g_m2);
    float* agg  = sym(g_agg);
    float* pool = sym(g_pool);
    float* z    = sym(g_z);
    unsigned* mask = (unsigned*)sym(g_mask);

    const int TPB = 256;
    const long long SNN = (long long)NN * NN;

    // adjacency mask
    zero_u32_k<<<(NN * MW + TPB - 1) / TPB, TPB>>>(mask, NN * MW);
    build_mask_k<<<(EE + TPB - 1) / TPB, TPB>>>(ei, mask);

    // h = relu(x @ Wi + bi)   [4096x256x512]
    tgemm_k<128,64,32,32,0,1><<<dim3(HDIM/64, NN/128, 1), 256>>>(
        x, IND, 0, Wi, HDIM, 0, h, HDIM, 0, IND, bi, 1, nullptr, 0);

    for (int l = 0; l < LL; l++) {
        const float* Wq_l  = Wq  + (size_t)l * HDIM * QD;
        const float* Wk_l  = Wk  + (size_t)l * HDIM * QD;
        const float* Wv_l  = Wv  + (size_t)l * HDIM * QD;
        const float* Bc_l  = Bc  + (size_t)l * QD * QD;
        const float* ce_l  = cemb + (size_t)l * 50 * QD;
        const float* Win_l = Win + (size_t)l * QD * 3 * QD;
        const float* bin_l = binp + (size_t)l * 3 * QD;
        const float* Wo_l  = Wo  + (size_t)l * QD * QD;
        const float* Wm1_l = Wm1 + (size_t)l * (2 * HDIM + QD) * QD;
        const float* Wm2_l = Wm2 + (size_t)l * QD * QD;
        const float* Wm3_l = Wm3 + (size_t)l * QD * HDIM;

        dim3 gNode(QD/64, NN/128, 1);   // 128x64 tiles -> 128 blocks

        // Q/K/V projections
        tgemm_k<128,64,32,32,0,1><<<gNode, 256>>>(h, HDIM, 0, Wq_l, QD, 0, Qt, QD, 0,
                                                  HDIM, bq + l * QD, 0, nullptr, 0);
        tgemm_k<128,64,32,32,0,1><<<gNode, 256>>>(h, HDIM, 0, Wk_l, QD, 0, Kt, QD, 0,
                                                  HDIM, bk + l * QD, 0, nullptr, 0);
        tgemm_k<128,64,32,32,0,1><<<gNode, 256>>>(h, HDIM, 0, Wv_l, QD, 0, V, QD, 0,
                                                  HDIM, bv + l * QD, 0, nullptr, 0);
        // biological constraint: Q = Qt@Bc, K = Kt@Bc^T
        tgemm_k<128,64,32,32,0,1><<<gNode, 256>>>(Qt, QD, 0, Bc_l, QD, 0, Q, QD, 0,
                                                  QD, nullptr, 0, nullptr, 0);
        tgemm_k<128,64,32,32,1,1><<<gNode, 256>>>(Kt, QD, 0, Bc_l, QD, 0, K, QD, 0,
                                                  QD, nullptr, 0, nullptr, 0);
        add_ce_k<<<(NN * QD / 4 + TPB - 1) / TPB, TPB>>>((float4*)Q, (float4*)K,
                                                         (const float4*)ce_l, ct);

        // graph-masked dense attention
        tgemm_k<128,128,64,32,1,1><<<dim3(NN/128, NN/128, 1), 256>>>(
            Q, QD, 0, K, QD, 0, S, NN, 0, QD, nullptr, 0, nullptr, 0);
        masked_softmax_k<<<NN, 256>>>(S, mask, rs, 0.0625f);          // 1/sqrt(256)
        zero_f32_k<<<(NN * QD + TPB - 1) / TPB, TPB>>>(gatt, NN * QD);
        tgemm_k<128,128,64,32,0,4><<<dim3(QD/128, NN/128, 4), 256>>>(
            S, NN, 0, V, QD, 0, gatt, QD, 0, NN, nullptr, 0, rs, 0);

        // MHA input projections
        tgemm_k<128,64,32,32,0,1><<<gNode, 256>>>(Q, QD, 0, Win_l, 3*QD, 0, mq, QD, 0,
                                                  QD, bin_l, 0, nullptr, 0);
        tgemm_k<128,64,32,32,0,1><<<gNode, 256>>>(K, QD, 0, Win_l + QD, 3*QD, 0, mk, QD, 0,
                                                  QD, bin_l + QD, 0, nullptr, 0);
        tgemm_k<128,64,32,32,0,1><<<gNode, 256>>>(V, QD, 0, Win_l + 2*QD, 3*QD, 0, mv, QD, 0,
                                                  QD, bin_l + 2*QD, 0, nullptr, 0);

        // batched per-head scores: Sh[h] = mq_h @ mk_h^T  (K=32)
        tgemm_k<128,128,64,32,1,1><<<dim3(NN/128, NN/128, NHD), 256>>>(
            mq, QD, HD, mk, QD, HD, Sh, NN, SNN, 32, nullptr, 0, nullptr, 0);
        softmax_h_k<<<dim3(NN, NHD), 256>>>(Sh, rsh, 0.17677669529663687f); // 1/sqrt(32)
        // batched per-head attn@V (rows scaled by inv-sums)
        tgemm_k<128,32,32,16,0,1><<<dim3(1, NN/128, NHD), 256>>>(
            Sh, NN, SNN, mv, QD, HD, mo, QD, HD, NN, nullptr, 0, rsh, NN);

        tgemm_k<128,64,32,32,0,1><<<gNode, 256>>>(mo, QD, 0, Wo_l, QD, 0, mha, QD, 0,
                                                  QD, bo + l * QD, 0, nullptr, 0);

        // edge message MLP (first layer factored through node GEMMs)
        tgemm_k<128,64,32,32,0,1><<<gNode, 256>>>(h, HDIM, 0, Wm1_l, QD, 0, eA, QD, 0,
                                                  HDIM, nullptr, 0, nullptr, 0);
        tgemm_k<128,64,32,32,0,1><<<gNode, 256>>>(h, HDIM, 0, Wm1_l + HDIM * QD, QD, 0,
                                                  eB, QD, 0, HDIM, nullptr, 0, nullptr, 0);
        edge_m1_k<<<(EE * QD / 4 + TPB - 1) / TPB, TPB>>>(
            (const float4*)eA, (const float4*)eB, ei, (const float4*)(bm1 + l * QD),
            (float4*)m1);
        tgemm_k<128,128,64,32,0,1><<<dim3(QD/128, EE/128, 1), 256>>>(
            m1, QD, 0, Wm2_l, QD, 0, m2, QD, 0, QD, bm2 + l * QD, 1, nullptr, 0);
        tgemm_k<128,128,64,32,0,1><<<dim3(HDIM/128, EE/128, 1), 256>>>(
            m2, QD, 0, Wm3_l, HDIM, 0, m1, HDIM, 0, QD, bm3 + l * HDIM, 0, nullptr, 0);
        zero_f32_k<<<(NN * HDIM + TPB - 1) / TPB, TPB>>>(agg, NN * HDIM);
        scatter_k<<<(EE * HDIM / 4 + TPB - 1) / TPB, TPB>>>((const float4*)m1, ei, agg);

        // residual + aggregate + LN
        combine_ln_k<<<NN, HDIM>>>(h, agg, mha, gatt, lng + l * HDIM, lnb + l * HDIM);
    }

    // readout
    pool_k<<<2 * HDIM, 256>>>(h, pool);
    fc1_k<<<HDIM, 256>>>(pool, Wc1, bc1, z);
    fc2_k<<<OUTD, 256>>>(z, Wc2, bc2, out);
}

// round 5
// speedup vs baseline: 4.8401x; 1.2620x over previous
#include <cuda_runtime.h>
#include <math.h>

// ---------------- problem constants ----------------
#define NN   4096
#define EE   65536
#define IND  512
#define HDIM 256
#define QD   256
#define NHD  8
#define HD   32
#define OUTD 10
#define LL   2
#define MW   (NN/32)   // mask words per row

// ---------------- static scratch (device globals; no runtime alloc) ----------------
__device__ float    g_h   [NN*HDIM];
__device__ float    g_Qt  [NN*QD];
__device__ float    g_Kt  [NN*QD];
__device__ float    g_Q   [NN*QD];
__device__ float    g_K   [NN*QD];
__device__ float    g_V   [NN*QD];
__device__ float    g_S   [(size_t)NN*NN];          // graph scores (64MB)
__device__ float    g_Sh  [(size_t)NHD*NN*NN];      // per-head scores (512MB)
__device__ float    g_rs  [NN];                     // graph softmax inv-sums
__device__ float    g_rsh [NHD*NN];                 // head softmax inv-sums
__device__ float    g_gatt[NN*QD];
__device__ float    g_mq  [NN*QD];
__device__ float    g_mk  [NN*QD];
__device__ float    g_mv  [NN*QD];
__device__ float    g_mo  [NN*QD];
__device__ float    g_mha [NN*QD];
__device__ float    g_eA  [NN*QD];
__device__ float    g_eB  [NN*QD];
__device__ float    g_m1  [(size_t)EE*QD];          // 64MB (also reused for m3)
__device__ float    g_m2  [(size_t)EE*QD];          // 64MB
__device__ unsigned g_mask[(size_t)NN*MW];
__device__ float    g_agg [NN*HDIM];
__device__ float    g_pool[2*HDIM];
__device__ float    g_z   [HDIM];

// =====================================================================
// TF32 tensor-core GEMM, 3-stage cp.async pipeline.
//  C[M,N] = act( A[M,K] * op(B) + bias ) * rowScale
//  op(B)=B[K,N] (TRANSB=0) or B^T with B stored [N,K] (TRANSB=1)
//  blockIdx.z: batch (SPLITK==1) or K-split (SPLITK>1; atomic C, caller zeros
//  C and passes bias=nullptr, act=0).
//  Caller guarantees: M%BM==0, N%BN==0, K%32==0, 16B-aligned pointers, ld%4==0.
// =====================================================================
__device__ __forceinline__ unsigned f2tf(float f) {
    unsigned u;
    asm("cvt.rna.tf32.f32 %0, %1;" : "=r"(u) : "f"(f));
    return u;
}
__device__ __forceinline__ void mma_tf32(float* c, const unsigned* a, const unsigned* b) {
    asm volatile(
        "mma.sync.aligned.m16n8k8.row.col.f32.tf32.tf32.f32 "
        "{%0,%1,%2,%3}, {%4,%5,%6,%7}, {%8,%9}, {%0,%1,%2,%3};"
        : "+f"(c[0]), "+f"(c[1]), "+f"(c[2]), "+f"(c[3])
        : "r"(a[0]), "r"(a[1]), "r"(a[2]), "r"(a[3]), "r"(b[0]), "r"(b[1]));
}
__device__ __forceinline__ void cpasync16(void* sdst, const void* gsrc) {
    unsigned sa = (unsigned)__cvta_generic_to_shared(sdst);
    asm volatile("cp.async.cg.shared.global [%0], [%1], 16;\n" :: "r"(sa), "l"(gsrc));
}
#define CP_COMMIT() asm volatile("cp.async.commit_group;\n" ::: "memory")

template<int BM, int BN, int TRANSB, int STAGES>
constexpr size_t tg_smem() {
    return (size_t)STAGES * ((size_t)BM * 36 + (TRANSB ? (size_t)BN * 36
                                                       : (size_t)32 * (BN + 8))) * 4;
}

template<int BM, int BN, int WM, int WN, int TRANSB, int SPLITK, int STAGES>
__global__ __launch_bounds__(256)
void tgemm_k(const float* __restrict__ A, int lda, long long sA,
             const float* __restrict__ B, int ldb, long long sB,
             float* __restrict__ C, int ldc, long long sC,
             int K,
             const float* __restrict__ bias, int act,
             const float* __restrict__ rowScale, long long sRS)
{
    constexpr int BK   = 32;
    constexpr int WX   = BN / WN;
    constexpr int WY   = BM / WM;
    static_assert(WX * WY == 8, "8 warps");
    constexpr int MM   = WM / 16;
    constexpr int MN   = WN / 8;
    constexpr int AL   = BM * (BK / 4) / 256;        // float4/thread for A tile
    constexpr int BLt  = BN * (BK / 4) / 256;
    constexpr int BLn  = BK * (BN / 4) / 256;
    constexpr int ASTR = BK + 4;                     // floats (row stride, A & Btrans)
    constexpr int BNSTR= BN + 8;                     // floats (row stride, B non-trans)
    constexpr int ASZ  = BM * ASTR;
    constexpr int BSZ  = TRANSB ? BN * ASTR : BK * BNSTR;

    const int tid  = threadIdx.x;
    const int wid  = tid >> 5;
    const int lane = tid & 31;
    const int wx   = wid % WX;
    const int wy   = wid / WX;
    const int lg   = lane >> 2;
    const int lt   = lane & 3;
    const int m0   = blockIdx.y * BM;
    const int n0   = blockIdx.x * BN;

    const float* Ab;
    const float* Bb;
    float*       Cb;
    const float* rsb;
    int kbeg, kend;
    if (SPLITK > 1) {
        Ab = A; Bb = B; Cb = C; rsb = rowScale;
        int kc = K / SPLITK;
        kbeg = blockIdx.z * kc;
        kend = kbeg + kc;
    } else {
        Ab  = A + sA * blockIdx.z;
        Bb  = B + sB * blockIdx.z;
        Cb  = C + sC * blockIdx.z;
        rsb = rowScale ? rowScale + sRS * blockIdx.z : nullptr;
        kbeg = 0; kend = K;
    }

    extern __shared__ float smem[];
    float* AsBase = smem;
    float* BsBase = smem + (size_t)STAGES * ASZ;

    auto load_stage = [&](int s, int k0) {
        float* as = AsBase + (size_t)s * ASZ;
#pragma unroll
        for (int j = 0; j < AL; j++) {
            int idx = tid + j * 256;
            int m   = idx >> 3;            // BK/4 = 8
            int k4  = idx & 7;
            cpasync16(&as[m * ASTR + k4 * 4],
                      &Ab[(size_t)(m0 + m) * lda + k0 + k4 * 4]);
        }
        float* bs = BsBase + (size_t)s * BSZ;
        if (TRANSB) {
#pragma unroll
            for (int j = 0; j < BLt; j++) {
                int idx = tid + j * 256;
                int n   = idx >> 3;
                int k4  = idx & 7;
                cpasync16(&bs[n * ASTR + k4 * 4],
                          &Bb[(size_t)(n0 + n) * ldb + k0 + k4 * 4]);
            }
        } else {
#pragma unroll
            for (int j = 0; j < BLn; j++) {
                int idx = tid + j * 256;
                int k   = idx / (BN / 4);
                int n4  = idx % (BN / 4);
                cpasync16(&bs[k * BNSTR + n4 * 4],
                          &Bb[(size_t)(k0 + k) * ldb + n0 + n4 * 4]);
            }
        }
    };

    float acc[MM][MN][4];
#pragma unroll
    for (int i = 0; i < MM; i++)
#pragma unroll
        for (int j = 0; j < MN; j++)
#pragma unroll
            for (int c = 0; c < 4; c++) acc[i][j][c] = 0.f;

    const int ktiles = (kend - kbeg) / BK;

#pragma unroll
    for (int s = 0; s < STAGES - 1; s++) {
        if (s < ktiles) load_stage(s, kbeg + s * BK);
        CP_COMMIT();
    }

    for (int t = 0; t < ktiles; t++) {
        asm volatile("cp.async.wait_group %0;\n" :: "n"(STAGES - 2) : "memory");
        __syncthreads();

        int nt = t + STAGES - 1;
        if (nt < ktiles) load_stage(nt % STAGES, kbeg + nt * BK);
        CP_COMMIT();

        const float* as = AsBase + (size_t)(t % STAGES) * ASZ;
        const float* bs = BsBase + (size_t)(t % STAGES) * BSZ;

#pragma unroll
        for (int ks = 0; ks < BK / 8; ks++) {
            const int kk = ks * 8;
            unsigned af[MM][4], bf[MN][2];
#pragma unroll
            for (int i = 0; i < MM; i++) {
                int row = wy * WM + i * 16 + lg;
                af[i][0] = f2tf(as[row * ASTR + kk + lt]);
                af[i][1] = f2tf(as[(row + 8) * ASTR + kk + lt]);
                af[i][2] = f2tf(as[row * ASTR + kk + lt + 4]);
                af[i][3] = f2tf(as[(row + 8) * ASTR + kk + lt + 4]);
            }
#pragma unroll
            for (int j = 0; j < MN; j++) {
                int col = wx * WN + j * 8 + lg;
                if (TRANSB) {
                    bf[j][0] = f2tf(bs[col * ASTR + kk + lt]);
                    bf[j][1] = f2tf(bs[col * ASTR + kk + lt + 4]);
                } else {
                    bf[j][0] = f2tf(bs[(kk + lt) * BNSTR + col]);
                    bf[j][1] = f2tf(bs[(kk + lt + 4) * BNSTR + col]);
                }
            }
#pragma unroll
            for (int i = 0; i < MM; i++)
#pragma unroll
                for (int j = 0; j < MN; j++)
                    mma_tf32(acc[i][j], af[i], bf[j]);
        }
        __syncthreads();
    }

    // epilogue
#pragma unroll
    for (int i = 0; i < MM; i++) {
        int mA = m0 + wy * WM + i * 16 + lg;
        int mB = mA + 8;
        float rsA = rsb ? rsb[mA] : 1.f;
        float rsB = rsb ? rsb[mB] : 1.f;
#pragma unroll
        for (int j = 0; j < MN; j++) {
            int n = n0 + wx * WN + j * 8 + lt * 2;
            float b0 = bias ? bias[n] : 0.f;
            float b1 = bias ? bias[n + 1] : 0.f;
            float v0 = (acc[i][j][0] + b0) * rsA;
            float v1 = (acc[i][j][1] + b1) * rsA;
            float v2 = (acc[i][j][2] + b0) * rsB;
            float v3 = (acc[i][j][3] + b1) * rsB;
            if (act == 1) {
                v0 = fmaxf(v0, 0.f); v1 = fmaxf(v1, 0.f);
                v2 = fmaxf(v2, 0.f); v3 = fmaxf(v3, 0.f);
            }
            if (SPLITK > 1) {
                atomicAdd(&Cb[(size_t)mA * ldc + n],     v0);
                atomicAdd(&Cb[(size_t)mA * ldc + n + 1], v1);
                atomicAdd(&Cb[(size_t)mB * ldc + n],     v2);
                atomicAdd(&Cb[(size_t)mB * ldc + n + 1], v3);
            } else {
                Cb[(size_t)mA * ldc + n]     = v0;
                Cb[(size_t)mA * ldc + n + 1] = v1;
                Cb[(size_t)mB * ldc + n]     = v2;
                Cb[(size_t)mB * ldc + n + 1] = v3;
            }
        }
    }
}

// ---------------- block reductions (256 threads) ----------------
__device__ __forceinline__ float blkMax(float v) {
    __shared__ float sh[8];
#pragma unroll
    for (int o = 16; o; o >>= 1) v = fmaxf(v, __shfl_xor_sync(0xffffffffu, v, o));
    if ((threadIdx.x & 31) == 0) sh[threadIdx.x >> 5] = v;
    __syncthreads();
    if (threadIdx.x < 32) {
        float w = (threadIdx.x < 8) ? sh[threadIdx.x] : -3.4e38f;
#pragma unroll
        for (int o = 4; o; o >>= 1) w = fmaxf(w, __shfl_xor_sync(0xffffffffu, w, o));
        if (threadIdx.x == 0) sh[0] = w;
    }
    __syncthreads();
    float r = sh[0];
    __syncthreads();
    return r;
}
__device__ __forceinline__ float blkSum(float v) {
    __shared__ float sh[8];
#pragma unroll
    for (int o = 16; o; o >>= 1) v += __shfl_xor_sync(0xffffffffu, v, o);
    if ((threadIdx.x & 31) == 0) sh[threadIdx.x >> 5] = v;
    __syncthreads();
    if (threadIdx.x < 32) {
        float w = (threadIdx.x < 8) ? sh[threadIdx.x] : 0.f;
#pragma unroll
        for (int o = 4; o; o >>= 1) w += __shfl_xor_sync(0xffffffffu, w, o);
        if (threadIdx.x == 0) sh[0] = w;
    }
    __syncthreads();
    float r = sh[0];
    __syncthreads();
    return r;
}

// ---------------- elementwise / reduction kernels ----------------
__global__ void zero_u32_k(unsigned* __restrict__ p, int n) {
    int i = blockIdx.x * blockDim.x + threadIdx.x;
    if (i < n) p[i] = 0u;
}
__global__ void zero_f32_k(float* __restrict__ p, int n) {
    int i = blockIdx.x * blockDim.x + threadIdx.x;
    if (i < n) p[i] = 0.f;
}
__global__ void build_mask_k(const int* __restrict__ ei, unsigned* __restrict__ mask) {
    int e = blockIdx.x * blockDim.x + threadIdx.x;
    if (e >= EE) return;
    int s = ei[e], t = ei[EE + e];
    atomicOr(&mask[(size_t)s * MW + (t >> 5)], 1u << (t & 31));
}
__global__ void add_ce_k(float4* __restrict__ Q, float4* __restrict__ K,
                         const float4* __restrict__ ce, const int* __restrict__ ct) {
    int idx = blockIdx.x * blockDim.x + threadIdx.x;       // NN*64
    if (idx >= NN * (QD / 4)) return;
    int i = idx >> 6, j4 = idx & 63;
    float4 c = ce[ct[i] * (QD / 4) + j4];
    float4 q = Q[idx], k = K[idx];
    q.x += 0.1f * c.x; q.y += 0.1f * c.y; q.z += 0.1f * c.z; q.w += 0.1f * c.w;
    k.x += 0.1f * c.x; k.y += 0.1f * c.y; k.z += 0.1f * c.z; k.w += 0.1f * c.w;
    Q[idx] = q; K[idx] = k;
}

// graph-masked softmax: writes UNNORMALIZED exp, inv-sum to rs[r]
__global__ void masked_softmax_k(float* __restrict__ S, const unsigned* __restrict__ mask,
                                 float* __restrict__ rs, float scale) {
    int r = blockIdx.x, t = threadIdx.x;
    const unsigned* mrow = mask + (size_t)r * MW;
    float4* row = reinterpret_cast<float4*>(S + (size_t)r * NN);

    float mx = -3.4e38f;
    for (int c4 = t; c4 < NN / 4; c4 += 256) {
        float4 v = row[c4];
        unsigned w = mrow[c4 >> 3];
        int off = (c4 & 7) * 4;
        float a0 = ((w >> (off + 0)) & 1u) ? v.x * scale : -1e9f;
        float a1 = ((w >> (off + 1)) & 1u) ? v.y * scale : -1e9f;
        float a2 = ((w >> (off + 2)) & 1u) ? v.z * scale : -1e9f;
        float a3 = ((w >> (off + 3)) & 1u) ? v.w * scale : -1e9f;
        mx = fmaxf(mx, fmaxf(fmaxf(a0, a1), fmaxf(a2, a3)));
    }
    mx = blkMax(mx);

    float sum = 0.f;
    for (int c4 = t; c4 < NN / 4; c4 += 256) {
        float4 v = row[c4];
        unsigned w = mrow[c4 >> 3];
        int off = (c4 & 7) * 4;
        float a0 = ((w >> (off + 0)) & 1u) ? v.x * scale : -1e9f;
        float a1 = ((w >> (off + 1)) & 1u) ? v.y * scale : -1e9f;
        float a2 = ((w >> (off + 2)) & 1u) ? v.z * scale : -1e9f;
        float a3 = ((w >> (off + 3)) & 1u) ? v.w * scale : -1e9f;
        float4 e;
        e.x = __expf(a0 - mx); e.y = __expf(a1 - mx);
        e.z = __expf(a2 - mx); e.w = __expf(a3 - mx);
        sum += e.x + e.y + e.z + e.w;
        row[c4] = e;
    }
    sum = blkSum(sum);
    if (t == 0) rs[r] = 1.f / sum;
}

// batched per-head softmax: blockIdx.x=row, blockIdx.y=head
__global__ void softmax_h_k(float* __restrict__ Sh, float* __restrict__ rsh, float scale) {
    int r = blockIdx.x, hh = blockIdx.y, t = threadIdx.x;
    float4* row = reinterpret_cast<float4*>(Sh + (size_t)hh * NN * NN + (size_t)r * NN);

    float mx = -3.4e38f;
    for (int c4 = t; c4 < NN / 4; c4 += 256) {
        float4 v = row[c4];
        mx = fmaxf(mx, fmaxf(fmaxf(v.x, v.y), fmaxf(v.z, v.w)));
    }
    mx = blkMax(mx) * scale;

    float sum = 0.f;
    for (int c4 = t; c4 < NN / 4; c4 += 256) {
        float4 v = row[c4];
        float4 e;
        e.x = __expf(v.x * scale - mx); e.y = __expf(v.y * scale - mx);
        e.z = __expf(v.z * scale - mx); e.w = __expf(v.w * scale - mx);
        sum += e.x + e.y + e.z + e.w;
        row[c4] = e;
    }
    sum = blkSum(sum);
    if (t == 0) rsh[hh * NN + r] = 1.f / sum;
}

// m1[e] = relu(eA[tgt[e]] + eB[src[e]] + bm1)   (float4)
__global__ void edge_m1_k(const float4* __restrict__ eA, const float4* __restrict__ eB,
                          const int* __restrict__ ei, const float4* __restrict__ bm1,
                          float4* __restrict__ m1) {
    int idx = blockIdx.x * blockDim.x + threadIdx.x;       // EE*64
    if (idx >= EE * (QD / 4)) return;
    int e = idx >> 6, j4 = idx & 63;
    int t = ei[EE + e], s = ei[e];
    float4 a = eA[t * (QD / 4) + j4];
    float4 b = eB[s * (QD / 4) + j4];
    float4 c = bm1[j4];
    float4 r;
    r.x = fmaxf(a.x + b.x + c.x, 0.f);
    r.y = fmaxf(a.y + b.y + c.y, 0.f);
    r.z = fmaxf(a.z + b.z + c.z, 0.f);
    r.w = fmaxf(a.w + b.w + c.w, 0.f);
    m1[idx] = r;
}

__global__ void scatter_k(const float4* __restrict__ m3, const int* __restrict__ ei,
                          float* __restrict__ agg) {
    int idx = blockIdx.x * blockDim.x + threadIdx.x;       // EE*64
    if (idx >= EE * (HDIM / 4)) return;
    int e = idx >> 6, j4 = idx & 63;
    float4 v = m3[idx];
    float* dst = agg + (size_t)ei[EE + e] * HDIM + j4 * 4;
    atomicAdd(dst + 0, v.x);
    atomicAdd(dst + 1, v.y);
    atomicAdd(dst + 2, v.z);
    atomicAdd(dst + 3, v.w);
}

// h = LN(res + agg + mha + gatt) * g + b
__global__ void combine_ln_k(float* __restrict__ h, const float* __restrict__ agg,
                             const float* __restrict__ mha, const float* __restrict__ gatt,
                             const float* __restrict__ g, const float* __restrict__ b) {
    int r = blockIdx.x, j = threadIdx.x;
    size_t idx = (size_t)r * HDIM + j;
    float v = h[idx] + agg[idx] + mha[idx] + gatt[idx];
    float mu = blkSum(v) * (1.f / HDIM);
    float d = v - mu;
    float var = blkSum(d * d) * (1.f / HDIM);
    h[idx] = d * rsqrtf(var + 1e-5f) * g[j] + b[j];
}

// pooled = concat(mean(h,0), max(h,0))
__global__ void pool_k(const float* __restrict__ h, float* __restrict__ pool) {
    int c = blockIdx.x, t = threadIdx.x;
    if (c < HDIM) {
        float s = 0.f;
        for (int r = t; r < NN; r += 256) s += h[(size_t)r * HDIM + c];
        s = blkSum(s);
        if (t == 0) pool[c] = s * (1.f / NN);
    } else {
        int cc = c - HDIM;
        float m = -3.4e38f;
        for (int r = t; r < NN; r += 256) m = fmaxf(m, h[(size_t)r * HDIM + cc]);
        m = blkMax(m);
        if (t == 0) pool[c] = m;
    }
}

__global__ void fc1_k(const float* __restrict__ pool, const float* __restrict__ W,
                      const float* __restrict__ b, float* __restrict__ z) {
    int o = blockIdx.x, t = threadIdx.x;
    float s = 0.f;
    for (int i = t; i < 2 * HDIM; i += 256) s += pool[i] * W[(size_t)i * HDIM + o];
    s = blkSum(s);
    if (t == 0) z[o] = fmaxf(s + b[o], 0.f);
}

__global__ void fc2_k(const float* __restrict__ z, const float* __restrict__ W,
                      const float* __restrict__ b, float* __restrict__ out) {
    int o = blockIdx.x, t = threadIdx.x;
    float s = 0.f;
    for (int i = t; i < HDIM; i += 256) s += z[i] * W[(size_t)i * OUTD + o];
    s = blkSum(s);
    if (t == 0) out[o] = s + b[o];
}

// ---------------- host side ----------------
static float* sym(const void* s) {
    void* p = nullptr;
    cudaGetSymbolAddress(&p, (const void*)s);
    return (float*)p;
}

// GEMM config shorthands (BM, BN, WM, WN)
#define BIG   128,128,64,32
#define NODE  64,128,32,32
#define HEADV 128,32,32,16

template<int BM,int BN,int WM,int WN,int TRANSB,int SPLITK,int STAGES>
static void launch_tg(dim3 grid,
                      const float* A, int lda, long long sA,
                      const float* B, int ldb, long long sB,
                      float* C, int ldc, long long sC, int K,
                      const float* bias, int act,
                      const float* rowScale, long long sRS)
{
    constexpr size_t sm = tg_smem<BM, BN, TRANSB, STAGES>();
    static bool attr_done = false;
    if (!attr_done) {
        cudaFuncSetAttribute(tgemm_k<BM,BN,WM,WN,TRANSB,SPLITK,STAGES>,
                             cudaFuncAttributeMaxDynamicSharedMemorySize, (int)sm);
        attr_done = true;
    }
    tgemm_k<BM,BN,WM,WN,TRANSB,SPLITK,STAGES><<<grid, 256, sm>>>(
        A, lda, sA, B, ldb, sB, C, ldc, sC, K, bias, act, rowScale, sRS);
}

extern "C" void kernel_launch(void* const* d_in, const int* in_sizes, int n_in,
                              void* d_out, int out_size) {
    const float* x    = (const float*)d_in[0];
    const int*   ei   = (const int*)  d_in[1];
    const int*   ct   = (const int*)  d_in[2];
    const float* Wi   = (const float*)d_in[3];
    const float* bi   = (const float*)d_in[4];
    const float* Wq   = (const float*)d_in[5];
    const float* bq   = (const float*)d_in[6];
    const float* Wk   = (const float*)d_in[7];
    const float* bk   = (const float*)d_in[8];
    const float* Wv   = (const float*)d_in[9];
    const float* bv   = (const float*)d_in[10];
    const float* Bc   = (const float*)d_in[11];
    const float* cemb = (const float*)d_in[12];
    const float* Win  = (const float*)d_in[13];
    const float* binp = (const float*)d_in[14];
    const float* Wo   = (const float*)d_in[15];
    const float* bo   = (const float*)d_in[16];
    const float* Wm1  = (const float*)d_in[17];
    const float* bm1  = (const float*)d_in[18];
    const float* Wm2  = (const float*)d_in[19];
    const float* bm2  = (const float*)d_in[20];
    const float* Wm3  = (const float*)d_in[21];
    const float* bm3  = (const float*)d_in[22];
    const float* lng  = (const float*)d_in[23];
    const float* lnb  = (const float*)d_in[24];
    const float* Wc1  = (const float*)d_in[25];
    const float* bc1  = (const float*)d_in[26];
    const float* Wc2  = (const float*)d_in[27];
    const float* bc2  = (const float*)d_in[28];
    float* out = (float*)d_out;

    float* h    = sym(g_h);
    float* Qt   = sym(g_Qt);
    float* Kt   = sym(g_Kt);
    float* Q    = sym(g_Q);
    float* K    = sym(g_K);
    float* V    = sym(g_V);
    float* S    = sym(g_S);
    float* Sh   = sym(g_Sh);
    float* rs   = sym(g_rs);
    float* rsh  = sym(g_rsh);
    float* gatt = sym(g_gatt);
    float* mq   = sym(g_mq);
    float* mk   = sym(g_mk);
    float* mv   = sym(g_mv);
    float* mo   = sym(g_mo);
    float* mha  = sym(g_mha);
    float* eA   = sym(g_eA);
    float* eB   = sym(g_eB);
    float* m1   = sym(g_m1);
    float* m2   = sym(g_m2);
    float* agg  = sym(g_agg);
    float* pool = sym(g_pool);
    float* z    = sym(g_z);
    unsigned* mask = (unsigned*)sym(g_mask);

    const int TPB = 256;
    const long long SNN = (long long)NN * NN;

    // adjacency mask
    zero_u32_k<<<(NN * MW + TPB - 1) / TPB, TPB>>>(mask, NN * MW);
    build_mask_k<<<(EE + TPB - 1) / TPB, TPB>>>(ei, mask);

    // h = relu(x @ Wi + bi)
    launch_tg<NODE,0,1,3>(dim3(HDIM/128, NN/64, 1),
        x, IND, 0, Wi, HDIM, 0, h, HDIM, 0, IND, bi, 1, nullptr, 0);

    for (int l = 0; l < LL; l++) {
        const float* Wq_l  = Wq  + (size_t)l * HDIM * QD;
        const float* Wk_l  = Wk  + (size_t)l * HDIM * QD;
        const float* Wv_l  = Wv  + (size_t)l * HDIM * QD;
        const float* Bc_l  = Bc  + (size_t)l * QD * QD;
        const float* ce_l  = cemb + (size_t)l * 50 * QD;
        const float* Win_l = Win + (size_t)l * QD * 3 * QD;
        const float* bin_l = binp + (size_t)l * 3 * QD;
        const float* Wo_l  = Wo  + (size_t)l * QD * QD;
        const float* Wm1_l = Wm1 + (size_t)l * (2 * HDIM + QD) * QD;
        const float* Wm2_l = Wm2 + (size_t)l * QD * QD;
        const float* Wm3_l = Wm3 + (size_t)l * QD * HDIM;

        dim3 gNode(QD/128, NN/64, 1);   // 64x128 tiles -> 128 blocks

        // Q/K/V projections
        launch_tg<NODE,0,1,3>(gNode, h, HDIM, 0, Wq_l, QD, 0, Qt, QD, 0,
                              HDIM, bq + l * QD, 0, nullptr, 0);
        launch_tg<NODE,0,1,3>(gNode, h, HDIM, 0, Wk_l, QD, 0, Kt, QD, 0,
                              HDIM, bk + l * QD, 0, nullptr, 0);
        launch_tg<NODE,0,1,3>(gNode, h, HDIM, 0, Wv_l, QD, 0, V, QD, 0,
                              HDIM, bv + l * QD, 0, nullptr, 0);
        // biological constraint: Q = Qt@Bc, K = Kt@Bc^T
        launch_tg<NODE,0,1,3>(gNode, Qt, QD, 0, Bc_l, QD, 0, Q, QD, 0,
                              QD, nullptr, 0, nullptr, 0);
        launch_tg<NODE,1,1,3>(gNode, Kt, QD, 0, Bc_l, QD, 0, K, QD, 0,
                              QD, nullptr, 0, nullptr, 0);
        add_ce_k<<<(NN * QD / 4 + TPB - 1) / TPB, TPB>>>((float4*)Q, (float4*)K,
                                                         (const float4*)ce_l, ct);

        // graph-masked dense attention
        launch_tg<BIG,1,1,3>(dim3(NN/128, NN/128, 1),
            Q, QD, 0, K, QD, 0, S, NN, 0, QD, nullptr, 0, nullptr, 0);
        masked_softmax_k<<<NN, 256>>>(S, mask, rs, 0.0625f);          // 1/sqrt(256)
        zero_f32_k<<<(NN * QD + TPB - 1) / TPB, TPB>>>(gatt, NN * QD);
        launch_tg<BIG,0,4,3>(dim3(QD/128, NN/128, 4),
            S, NN, 0, V, QD, 0, gatt, QD, 0, NN, nullptr, 0, rs, 0);

        // MHA input projections
        launch_tg<NODE,0,1,3>(gNode, Q, QD, 0, Win_l, 3*QD, 0, mq, QD, 0,
                              QD, bin_l, 0, nullptr, 0);
        launch_tg<NODE,0,1,3>(gNode, K, QD, 0, Win_l + QD, 3*QD, 0, mk, QD, 0,
                              QD, bin_l + QD, 0, nullptr, 0);
        launch_tg<NODE,0,1,3>(gNode, V, QD, 0, Win_l + 2*QD, 3*QD, 0, mv, QD, 0,
                              QD, bin_l + 2*QD, 0, nullptr, 0);

        // batched per-head scores: Sh[h] = mq_h @ mk_h^T  (K=32)
        launch_tg<BIG,1,1,3>(dim3(NN/128, NN/128, NHD),
            mq, QD, HD, mk, QD, HD, Sh, NN, SNN, 32, nullptr, 0, nullptr, 0);
        softmax_h_k<<<dim3(NN, NHD), 256>>>(Sh, rsh, 0.17677669529663687f); // 1/sqrt(32)
        // batched per-head attn@V (rows scaled by inv-sums)
        launch_tg<HEADV,0,1,3>(dim3(1, NN/128, NHD),
            Sh, NN, SNN, mv, QD, HD, mo, QD, HD, NN, nullptr, 0, rsh, NN);

        launch_tg<NODE,0,1,3>(gNode, mo, QD, 0, Wo_l, QD, 0, mha, QD, 0,
                              QD, bo + l * QD, 0, nullptr, 0);

        // edge message MLP (first layer factored through node GEMMs)
        launch_tg<NODE,0,1,3>(gNode, h, HDIM, 0, Wm1_l, QD, 0, eA, QD, 0,
                              HDIM, nullptr, 0, nullptr, 0);
        launch_tg<NODE,0,1,3>(gNode, h, HDIM, 0, Wm1_l + HDIM * QD, QD, 0,
                              eB, QD, 0, HDIM, nullptr, 0, nullptr, 0);
        edge_m1_k<<<(EE * QD / 4 + TPB - 1) / TPB, TPB>>>(
            (const float4*)eA, (const float4*)eB, ei, (const float4*)(bm1 + l * QD),
            (float4*)m1);
        launch_tg<BIG,0,1,3>(dim3(QD/128, EE/128, 1),
            m1, QD, 0, Wm2_l, QD, 0, m2, QD, 0, QD, bm2 + l * QD, 1, nullptr, 0);
        launch_tg<BIG,0,1,3>(dim3(HDIM/128, EE/128, 1),
            m2, QD, 0, Wm3_l, HDIM, 0, m1, HDIM, 0, QD, bm3 + l * HDIM, 0, nullptr, 0);
        zero_f32_k<<<(NN * HDIM + TPB - 1) / TPB, TPB>>>(agg, NN * HDIM);
        scatter_k<<<(EE * HDIM / 4 + TPB - 1) / TPB, TPB>>>((const float4*)m1, ei, agg);

        // residual + aggregate + LN
        combine_ln_k<<<NN, HDIM>>>(h, agg, mha, gatt, lng + l * HDIM, lnb + l * HDIM);
    }

    // readout
    pool_k<<<2 * HDIM, 256>>>(h, pool);
    fc1_k<<<HDIM, 256>>>(pool, Wc1, bc1, z);
    fc2_k<<<OUTD, 256>>>(z, Wc2, bc2, out);
}

// round 6
// speedup vs baseline: 6.6601x; 1.3760x over previous
#include <cuda_runtime.h>
#include <math.h>

// ---------------- problem constants ----------------
#define NN   4096
#define EE   65536
#define IND  512
#define HDIM 256
#define QD   256
#define NHD  8
#define HD   32
#define OUTD 10
#define LL   2
#define MW   (NN/32)   // mask words per row

// ---------------- static scratch (device globals; no runtime alloc) ----------------
__device__ float    g_h   [NN*HDIM];
__device__ float    g_Qt  [NN*QD];
__device__ float    g_Kt  [NN*QD];
__device__ float    g_Q   [NN*QD];
__device__ float    g_K   [NN*QD];
__device__ float    g_V   [NN*QD];
__device__ float    g_S   [(size_t)NN*NN];          // graph scores (64MB)
__device__ float    g_rs  [NN];                     // graph softmax inv-sums
__device__ float    g_gatt[NN*QD];
__device__ float    g_mq  [NN*QD];
__device__ float    g_mk  [NN*QD];
__device__ float    g_mv  [NN*QD];
__device__ float    g_mo  [NN*QD];
__device__ float    g_mha [NN*QD];
__device__ float    g_eA  [NN*QD];
__device__ float    g_eB  [NN*QD];
__device__ float    g_m1  [(size_t)EE*QD];          // 64MB (also reused for m3)
__device__ float    g_m2  [(size_t)EE*QD];          // 64MB
__device__ unsigned g_mask[(size_t)NN*MW];
__device__ float    g_agg [NN*HDIM];
__device__ float    g_pool[2*HDIM];
__device__ float    g_z   [HDIM];

// ---------------- TF32 helpers ----------------
__device__ __forceinline__ unsigned f2tf(float f) {
    unsigned u;
    asm("cvt.rna.tf32.f32 %0, %1;" : "=r"(u) : "f"(f));
    return u;
}
__device__ __forceinline__ void mma_tf32(float* c, const unsigned* a, const unsigned* b) {
    asm volatile(
        "mma.sync.aligned.m16n8k8.row.col.f32.tf32.tf32.f32 "
        "{%0,%1,%2,%3}, {%4,%5,%6,%7}, {%8,%9}, {%0,%1,%2,%3};"
        : "+f"(c[0]), "+f"(c[1]), "+f"(c[2]), "+f"(c[3])
        : "r"(a[0]), "r"(a[1]), "r"(a[2]), "r"(a[3]), "r"(b[0]), "r"(b[1]));
}
__device__ __forceinline__ void cpasync16(void* sdst, const void* gsrc) {
    unsigned sa = (unsigned)__cvta_generic_to_shared(sdst);
    asm volatile("cp.async.cg.shared.global [%0], [%1], 16;\n" :: "r"(sa), "l"(gsrc));
}
#define CP_COMMIT() asm volatile("cp.async.commit_group;\n" ::: "memory")

// =====================================================================
// TF32 tensor-core GEMM, cp.async pipeline (unchanged from round 5)
// =====================================================================
template<int BM, int BN, int TRANSB, int STAGES>
constexpr size_t tg_smem() {
    return (size_t)STAGES * ((size_t)BM * 36 + (TRANSB ? (size_t)BN * 36
                                                       : (size_t)32 * (BN + 8))) * 4;
}

template<int BM, int BN, int WM, int WN, int TRANSB, int SPLITK, int STAGES>
__global__ __launch_bounds__(256)
void tgemm_k(const float* __restrict__ A, int lda, long long sA,
             const float* __restrict__ B, int ldb, long long sB,
             float* __restrict__ C, int ldc, long long sC,
             int K,
             const float* __restrict__ bias, int act,
             const float* __restrict__ rowScale, long long sRS)
{
    constexpr int BK   = 32;
    constexpr int WX   = BN / WN;
    constexpr int WY   = BM / WM;
    static_assert(WX * WY == 8, "8 warps");
    constexpr int MM   = WM / 16;
    constexpr int MN   = WN / 8;
    constexpr int AL   = BM * (BK / 4) / 256;
    constexpr int BLt  = BN * (BK / 4) / 256;
    constexpr int BLn  = BK * (BN / 4) / 256;
    constexpr int ASTR = BK + 4;
    constexpr int BNSTR= BN + 8;
    constexpr int ASZ  = BM * ASTR;
    constexpr int BSZ  = TRANSB ? BN * ASTR : BK * BNSTR;

    const int tid  = threadIdx.x;
    const int wid  = tid >> 5;
    const int lane = tid & 31;
    const int wx   = wid % WX;
    const int wy   = wid / WX;
    const int lg   = lane >> 2;
    const int lt   = lane & 3;
    const int m0   = blockIdx.y * BM;
    const int n0   = blockIdx.x * BN;

    const float* Ab;
    const float* Bb;
    float*       Cb;
    const float* rsb;
    int kbeg, kend;
    if (SPLITK > 1) {
        Ab = A; Bb = B; Cb = C; rsb = rowScale;
        int kc = K / SPLITK;
        kbeg = blockIdx.z * kc;
        kend = kbeg + kc;
    } else {
        Ab  = A + sA * blockIdx.z;
        Bb  = B + sB * blockIdx.z;
        Cb  = C + sC * blockIdx.z;
        rsb = rowScale ? rowScale + sRS * blockIdx.z : nullptr;
        kbeg = 0; kend = K;
    }

    extern __shared__ float smem[];
    float* AsBase = smem;
    float* BsBase = smem + (size_t)STAGES * ASZ;

    auto load_stage = [&](int s, int k0) {
        float* as = AsBase + (size_t)s * ASZ;
#pragma unroll
        for (int j = 0; j < AL; j++) {
            int idx = tid + j * 256;
            int m   = idx >> 3;
            int k4  = idx & 7;
            cpasync16(&as[m * ASTR + k4 * 4],
                      &Ab[(size_t)(m0 + m) * lda + k0 + k4 * 4]);
        }
        float* bs = BsBase + (size_t)s * BSZ;
        if (TRANSB) {
#pragma unroll
            for (int j = 0; j < BLt; j++) {
                int idx = tid + j * 256;
                int n   = idx >> 3;
                int k4  = idx & 7;
                cpasync16(&bs[n * ASTR + k4 * 4],
                          &Bb[(size_t)(n0 + n) * ldb + k0 + k4 * 4]);
            }
        } else {
#pragma unroll
            for (int j = 0; j < BLn; j++) {
                int idx = tid + j * 256;
                int k   = idx / (BN / 4);
                int n4  = idx % (BN / 4);
                cpasync16(&bs[k * BNSTR + n4 * 4],
                          &Bb[(size_t)(k0 + k) * ldb + n0 + n4 * 4]);
            }
        }
    };

    float acc[MM][MN][4];
#pragma unroll
    for (int i = 0; i < MM; i++)
#pragma unroll
        for (int j = 0; j < MN; j++)
#pragma unroll
            for (int c = 0; c < 4; c++) acc[i][j][c] = 0.f;

    const int ktiles = (kend - kbeg) / BK;

#pragma unroll
    for (int s = 0; s < STAGES - 1; s++) {
        if (s < ktiles) load_stage(s, kbeg + s * BK);
        CP_COMMIT();
    }

    for (int t = 0; t < ktiles; t++) {
        asm volatile("cp.async.wait_group %0;\n" :: "n"(STAGES - 2) : "memory");
        __syncthreads();

        int nt = t + STAGES - 1;
        if (nt < ktiles) load_stage(nt % STAGES, kbeg + nt * BK);
        CP_COMMIT();

        const float* as = AsBase + (size_t)(t % STAGES) * ASZ;
        const float* bs = BsBase + (size_t)(t % STAGES) * BSZ;

#pragma unroll
        for (int ks = 0; ks < BK / 8; ks++) {
            const int kk = ks * 8;
            unsigned af[MM][4], bf[MN][2];
#pragma unroll
            for (int i = 0; i < MM; i++) {
                int row = wy * WM + i * 16 + lg;
                af[i][0] = f2tf(as[row * ASTR + kk + lt]);
                af[i][1] = f2tf(as[(row + 8) * ASTR + kk + lt]);
                af[i][2] = f2tf(as[row * ASTR + kk + lt + 4]);
                af[i][3] = f2tf(as[(row + 8) * ASTR + kk + lt + 4]);
            }
#pragma unroll
            for (int j = 0; j < MN; j++) {
                int col = wx * WN + j * 8 + lg;
                if (TRANSB) {
                    bf[j][0] = f2tf(bs[col * ASTR + kk + lt]);
                    bf[j][1] = f2tf(bs[col * ASTR + kk + lt + 4]);
                } else {
                    bf[j][0] = f2tf(bs[(kk + lt) * BNSTR + col]);
                    bf[j][1] = f2tf(bs[(kk + lt + 4) * BNSTR + col]);
                }
            }
#pragma unroll
            for (int i = 0; i < MM; i++)
#pragma unroll
                for (int j = 0; j < MN; j++)
                    mma_tf32(acc[i][j], af[i], bf[j]);
        }
        __syncthreads();
    }

#pragma unroll
    for (int i = 0; i < MM; i++) {
        int mA = m0 + wy * WM + i * 16 + lg;
        int mB = mA + 8;
        float rsA = rsb ? rsb[mA] : 1.f;
        float rsB = rsb ? rsb[mB] : 1.f;
#pragma unroll
        for (int j = 0; j < MN; j++) {
            int n = n0 + wx * WN + j * 8 + lt * 2;
            float b0 = bias ? bias[n] : 0.f;
            float b1 = bias ? bias[n + 1] : 0.f;
            float v0 = (acc[i][j][0] + b0) * rsA;
            float v1 = (acc[i][j][1] + b1) * rsA;
            float v2 = (acc[i][j][2] + b0) * rsB;
            float v3 = (acc[i][j][3] + b1) * rsB;
            if (act == 1) {
                v0 = fmaxf(v0, 0.f); v1 = fmaxf(v1, 0.f);
                v2 = fmaxf(v2, 0.f); v3 = fmaxf(v3, 0.f);
            }
            if (SPLITK > 1) {
                atomicAdd(&Cb[(size_t)mA * ldc + n],     v0);
                atomicAdd(&Cb[(size_t)mA * ldc + n + 1], v1);
                atomicAdd(&Cb[(size_t)mB * ldc + n],     v2);
                atomicAdd(&Cb[(size_t)mB * ldc + n + 1], v3);
            } else {
                Cb[(size_t)mA * ldc + n]     = v0;
                Cb[(size_t)mA * ldc + n + 1] = v1;
                Cb[(size_t)mB * ldc + n]     = v2;
                Cb[(size_t)mB * ldc + n + 1] = v3;
            }
        }
    }
}

// =====================================================================
// Flash MHA: per-head fused scores -> online softmax -> P@V.
//  grid (NN/128, NHD), 256 threads. Warp w handles query rows [w*16, w*16+16).
//  Q/K/V are column slices [hh*HD, hh*HD+HD) of [NN, QD] arrays.
// =====================================================================
#define FBQ   128
#define FBKV  64
#define QSTR  36        // conflict-free: A-frag addr = row*36 + k  -> lg*4+lt
#define KSTR  36        // conflict-free: B-frag addr = col*36 + k  -> lg*4+lt
#define VSTR  40        // conflict-free: B-frag addr = k*40 + col  -> lt*8+lg
#define PSTR  68        // conflict-free: A-frag addr = row*68 + k  -> lg*4+lt
#define FLASH_SMEM ((FBQ*QSTR + 2*FBKV*KSTR + 2*FBKV*VSTR + 8*16*PSTR) * 4)

__global__ __launch_bounds__(256)
void flash_mha_k(const float* __restrict__ mq, const float* __restrict__ mk,
                 const float* __restrict__ mv, float* __restrict__ mo, float scale)
{
    extern __shared__ float sm[];
    float*    Qs = sm;                            // [128][QSTR]
    float*    Ks = Qs + FBQ * QSTR;               // [2][64][KSTR]
    float*    Vs = Ks + 2 * FBKV * KSTR;          // [2][64][VSTR]
    unsigned* Ps = (unsigned*)(Vs + 2 * FBKV * VSTR); // [8][16][PSTR]

    const int tid  = threadIdx.x;
    const int wid  = tid >> 5;
    const int lane = tid & 31;
    const int lg   = lane >> 2;
    const int lt   = lane & 3;
    const int hh   = blockIdx.y;
    const int q0   = blockIdx.x * FBQ;

    const float* Qg = mq + (size_t)q0 * QD + hh * HD;
    const float* Kg = mk + hh * HD;
    const float* Vg = mv + hh * HD;

    // Q tile: 128 rows x 32 floats = 1024 float4 -> 4 per thread
#pragma unroll
    for (int j = 0; j < 4; j++) {
        int idx = tid + j * 256;
        int r = idx >> 3, c4 = idx & 7;
        cpasync16(&Qs[r * QSTR + c4 * 4], &Qg[(size_t)r * QD + c4 * 4]);
    }
    auto loadKV = [&](int s, int kv0) {
        float* ks = Ks + s * FBKV * KSTR;
        float* vs = Vs + s * FBKV * VSTR;
#pragma unroll
        for (int j = 0; j < 2; j++) {
            int idx = tid + j * 256;
            int r = idx >> 3, c4 = idx & 7;
            cpasync16(&ks[r * KSTR + c4 * 4], &Kg[(size_t)(kv0 + r) * QD + c4 * 4]);
        }
#pragma unroll
        for (int j = 0; j < 2; j++) {
            int idx = tid + j * 256;
            int r = idx >> 3, c4 = idx & 7;
            cpasync16(&vs[r * VSTR + c4 * 4], &Vg[(size_t)(kv0 + r) * QD + c4 * 4]);
        }
    };
    loadKV(0, 0);
    CP_COMMIT();

    float O[4][4];
#pragma unroll
    for (int j = 0; j < 4; j++)
#pragma unroll
        for (int c = 0; c < 4; c++) O[j][c] = 0.f;
    float m0r = -3.4e38f, m1r = -3.4e38f;   // running max, rows lg / lg+8
    float l0 = 0.f, l1 = 0.f;               // running sums
    unsigned* Pw = Ps + wid * 16 * PSTR;
    const int qrow = wid * 16 + lg;

    const int NT = NN / FBKV;
    for (int t = 0; t < NT; t++) {
        if (t + 1 < NT) loadKV((t + 1) & 1, (t + 1) * FBKV);
        CP_COMMIT();
        asm volatile("cp.async.wait_group 1;\n" ::: "memory");
        __syncthreads();

        const float* ks = Ks + (t & 1) * FBKV * KSTR;
        const float* vs = Vs + (t & 1) * FBKV * VSTR;

        // S = Q_w @ K^T  (16 x 64)
        float Sacc[8][4];
#pragma unroll
        for (int n = 0; n < 8; n++)
#pragma unroll
            for (int c = 0; c < 4; c++) Sacc[n][c] = 0.f;
#pragma unroll
        for (int ks8 = 0; ks8 < 4; ks8++) {
            const int kk = ks8 * 8;
            unsigned af[4];
            af[0] = f2tf(Qs[qrow * QSTR + kk + lt]);
            af[1] = f2tf(Qs[(qrow + 8) * QSTR + kk + lt]);
            af[2] = f2tf(Qs[qrow * QSTR + kk + lt + 4]);
            af[3] = f2tf(Qs[(qrow + 8) * QSTR + kk + lt + 4]);
#pragma unroll
            for (int n = 0; n < 8; n++) {
                int col = n * 8 + lg;
                unsigned bf[2];
                bf[0] = f2tf(ks[col * KSTR + kk + lt]);
                bf[1] = f2tf(ks[col * KSTR + kk + lt + 4]);
                mma_tf32(Sacc[n], af, bf);
            }
        }

        // online softmax on fragments (rows lg, lg+8)
        float mx0 = -3.4e38f, mx1 = -3.4e38f;
#pragma unroll
        for (int n = 0; n < 8; n++) {
            Sacc[n][0] *= scale; Sacc[n][1] *= scale;
            Sacc[n][2] *= scale; Sacc[n][3] *= scale;
            mx0 = fmaxf(mx0, fmaxf(Sacc[n][0], Sacc[n][1]));
            mx1 = fmaxf(mx1, fmaxf(Sacc[n][2], Sacc[n][3]));
        }
        mx0 = fmaxf(mx0, __shfl_xor_sync(0xffffffffu, mx0, 1));
        mx0 = fmaxf(mx0, __shfl_xor_sync(0xffffffffu, mx0, 2));
        mx1 = fmaxf(mx1, __shfl_xor_sync(0xffffffffu, mx1, 1));
        mx1 = fmaxf(mx1, __shfl_xor_sync(0xffffffffu, mx1, 2));
        float mn0 = fmaxf(m0r, mx0), mn1 = fmaxf(m1r, mx1);
        float a0 = __expf(m0r - mn0), a1 = __expf(m1r - mn1);
        float rs0 = 0.f, rs1 = 0.f;
#pragma unroll
        for (int n = 0; n < 8; n++) {
            float p0 = __expf(Sacc[n][0] - mn0);
            float p1 = __expf(Sacc[n][1] - mn0);
            float p2 = __expf(Sacc[n][2] - mn1);
            float p3 = __expf(Sacc[n][3] - mn1);
            rs0 += p0 + p1; rs1 += p2 + p3;
            int c0 = n * 8 + lt * 2;
            Pw[lg * PSTR + c0]           = f2tf(p0);
            Pw[lg * PSTR + c0 + 1]       = f2tf(p1);
            Pw[(lg + 8) * PSTR + c0]     = f2tf(p2);
            Pw[(lg + 8) * PSTR + c0 + 1] = f2tf(p3);
        }
        rs0 += __shfl_xor_sync(0xffffffffu, rs0, 1);
        rs0 += __shfl_xor_sync(0xffffffffu, rs0, 2);
        rs1 += __shfl_xor_sync(0xffffffffu, rs1, 1);
        rs1 += __shfl_xor_sync(0xffffffffu, rs1, 2);
        l0 = l0 * a0 + rs0;
        l1 = l1 * a1 + rs1;
        m0r = mn0; m1r = mn1;
#pragma unroll
        for (int j = 0; j < 4; j++) {
            O[j][0] *= a0; O[j][1] *= a0;
            O[j][2] *= a1; O[j][3] *= a1;
        }
        __syncwarp();

        // O += P @ V   (16 x 32, K = 64)
#pragma unroll
        for (int ks8 = 0; ks8 < 8; ks8++) {
            const int kk = ks8 * 8;
            unsigned af[4];
            af[0] = Pw[lg * PSTR + kk + lt];
            af[1] = Pw[(lg + 8) * PSTR + kk + lt];
            af[2] = Pw[lg * PSTR + kk + lt + 4];
            af[3] = Pw[(lg + 8) * PSTR + kk + lt + 4];
#pragma unroll
            for (int j = 0; j < 4; j++) {
                int col = j * 8 + lg;
                unsigned bf[2];
                bf[0] = f2tf(vs[(kk + lt) * VSTR + col]);
                bf[1] = f2tf(vs[(kk + lt + 4) * VSTR + col]);
                mma_tf32(O[j], af, bf);
            }
        }
        __syncwarp();
        __syncthreads();
    }

    // normalize and write head slice of mo
    float inv0 = 1.f / l0, inv1 = 1.f / l1;
    const size_t rA = (size_t)(q0 + qrow) * QD + hh * HD;
    const size_t rB = rA + 8 * QD;
#pragma unroll
    for (int j = 0; j < 4; j++) {
        int c = j * 8 + lt * 2;
        mo[rA + c]     = O[j][0] * inv0;
        mo[rA + c + 1] = O[j][1] * inv0;
        mo[rB + c]     = O[j][2] * inv1;
        mo[rB + c + 1] = O[j][3] * inv1;
    }
}

// ---------------- block reductions (256 threads) ----------------
__device__ __forceinline__ float blkMax(float v) {
    __shared__ float sh[8];
#pragma unroll
    for (int o = 16; o; o >>= 1) v = fmaxf(v, __shfl_xor_sync(0xffffffffu, v, o));
    if ((threadIdx.x & 31) == 0) sh[threadIdx.x >> 5] = v;
    __syncthreads();
    if (threadIdx.x < 32) {
        float w = (threadIdx.x < 8) ? sh[threadIdx.x] : -3.4e38f;
#pragma unroll
        for (int o = 4; o; o >>= 1) w = fmaxf(w, __shfl_xor_sync(0xffffffffu, w, o));
        if (threadIdx.x == 0) sh[0] = w;
    }
    __syncthreads();
    float r = sh[0];
    __syncthreads();
    return r;
}
__device__ __forceinline__ float blkSum(float v) {
    __shared__ float sh[8];
#pragma unroll
    for (int o = 16; o; o >>= 1) v += __shfl_xor_sync(0xffffffffu, v, o);
    if ((threadIdx.x & 31) == 0) sh[threadIdx.x >> 5] = v;
    __syncthreads();
    if (threadIdx.x < 32) {
        float w = (threadIdx.x < 8) ? sh[threadIdx.x] : 0.f;
#pragma unroll
        for (int o = 4; o; o >>= 1) w += __shfl_xor_sync(0xffffffffu, w, o);
        if (threadIdx.x == 0) sh[0] = w;
    }
    __syncthreads();
    float r = sh[0];
    __syncthreads();
    return r;
}

// ---------------- elementwise / reduction kernels ----------------
__global__ void zero_u32_k(unsigned* __restrict__ p, int n) {
    int i = blockIdx.x * blockDim.x + threadIdx.x;
    if (i < n) p[i] = 0u;
}
__global__ void zero_f32_k(float* __restrict__ p, int n) {
    int i = blockIdx.x * blockDim.x + threadIdx.x;
    if (i < n) p[i] = 0.f;
}
__global__ void build_mask_k(const int* __restrict__ ei, unsigned* __restrict__ mask) {
    int e = blockIdx.x * blockDim.x + threadIdx.x;
    if (e >= EE) return;
    int s = ei[e], t = ei[EE + e];
    atomicOr(&mask[(size_t)s * MW + (t >> 5)], 1u << (t & 31));
}
__global__ void add_ce_k(float4* __restrict__ Q, float4* __restrict__ K,
                         const float4* __restrict__ ce, const int* __restrict__ ct) {
    int idx = blockIdx.x * blockDim.x + threadIdx.x;
    if (idx >= NN * (QD / 4)) return;
    int i = idx >> 6, j4 = idx & 63;
    float4 c = ce[ct[i] * (QD / 4) + j4];
    float4 q = Q[idx], k = K[idx];
    q.x += 0.1f * c.x; q.y += 0.1f * c.y; q.z += 0.1f * c.z; q.w += 0.1f * c.w;
    k.x += 0.1f * c.x; k.y += 0.1f * c.y; k.z += 0.1f * c.z; k.w += 0.1f * c.w;
    Q[idx] = q; K[idx] = k;
}

// graph-masked softmax: writes UNNORMALIZED exp, inv-sum to rs[r]
__global__ void masked_softmax_k(float* __restrict__ S, const unsigned* __restrict__ mask,
                                 float* __restrict__ rs, float scale) {
    int r = blockIdx.x, t = threadIdx.x;
    const unsigned* mrow = mask + (size_t)r * MW;
    float4* row = reinterpret_cast<float4*>(S + (size_t)r * NN);

    float mx = -3.4e38f;
    for (int c4 = t; c4 < NN / 4; c4 += 256) {
        float4 v = row[c4];
        unsigned w = mrow[c4 >> 3];
        int off = (c4 & 7) * 4;
        float a0 = ((w >> (off + 0)) & 1u) ? v.x * scale : -1e9f;
        float a1 = ((w >> (off + 1)) & 1u) ? v.y * scale : -1e9f;
        float a2 = ((w >> (off + 2)) & 1u) ? v.z * scale : -1e9f;
        float a3 = ((w >> (off + 3)) & 1u) ? v.w * scale : -1e9f;
        mx = fmaxf(mx, fmaxf(fmaxf(a0, a1), fmaxf(a2, a3)));
    }
    mx = blkMax(mx);

    float sum = 0.f;
    for (int c4 = t; c4 < NN / 4; c4 += 256) {
        float4 v = row[c4];
        unsigned w = mrow[c4 >> 3];
        int off = (c4 & 7) * 4;
        float a0 = ((w >> (off + 0)) & 1u) ? v.x * scale : -1e9f;
        float a1 = ((w >> (off + 1)) & 1u) ? v.y * scale : -1e9f;
        float a2 = ((w >> (off + 2)) & 1u) ? v.z * scale : -1e9f;
        float a3 = ((w >> (off + 3)) & 1u) ? v.w * scale : -1e9f;
        float4 e;
        e.x = __expf(a0 - mx); e.y = __expf(a1 - mx);
        e.z = __expf(a2 - mx); e.w = __expf(a3 - mx);
        sum += e.x + e.y + e.z + e.w;
        row[c4] = e;
    }
    sum = blkSum(sum);
    if (t == 0) rs[r] = 1.f / sum;
}

// m1[e] = relu(eA[tgt[e]] + eB[src[e]] + bm1)   (float4)
__global__ void edge_m1_k(const float4* __restrict__ eA, const float4* __restrict__ eB,
                          const int* __restrict__ ei, const float4* __restrict__ bm1,
                          float4* __restrict__ m1) {
    int idx = blockIdx.x * blockDim.x + threadIdx.x;
    if (idx >= EE * (QD / 4)) return;
    int e = idx >> 6, j4 = idx & 63;
    int t = ei[EE + e], s = ei[e];
    float4 a = eA[t * (QD / 4) + j4];
    float4 b = eB[s * (QD / 4) + j4];
    float4 c = bm1[j4];
    float4 r;
    r.x = fmaxf(a.x + b.x + c.x, 0.f);
    r.y = fmaxf(a.y + b.y + c.y, 0.f);
    r.z = fmaxf(a.z + b.z + c.z, 0.f);
    r.w = fmaxf(a.w + b.w + c.w, 0.f);
    m1[idx] = r;
}

__global__ void scatter_k(const float4* __restrict__ m3, const int* __restrict__ ei,
                          float* __restrict__ agg) {
    int idx = blockIdx.x * blockDim.x + threadIdx.x;
    if (idx >= EE * (HDIM / 4)) return;
    int e = idx >> 6, j4 = idx & 63;
    float4 v = m3[idx];
    float* dst = agg + (size_t)ei[EE + e] * HDIM + j4 * 4;
    atomicAdd(dst + 0, v.x);
    atomicAdd(dst + 1, v.y);
    atomicAdd(dst + 2, v.z);
    atomicAdd(dst + 3, v.w);
}

// h = LN(res + agg + mha + gatt) * g + b
__global__ void combine_ln_k(float* __restrict__ h, const float* __restrict__ agg,
                             const float* __restrict__ mha, const float* __restrict__ gatt,
                             const float* __restrict__ g, const float* __restrict__ b) {
    int r = blockIdx.x, j = threadIdx.x;
    size_t idx = (size_t)r * HDIM + j;
    float v = h[idx] + agg[idx] + mha[idx] + gatt[idx];
    float mu = blkSum(v) * (1.f / HDIM);
    float d = v - mu;
    float var = blkSum(d * d) * (1.f / HDIM);
    h[idx] = d * rsqrtf(var + 1e-5f) * g[j] + b[j];
}

// pooled = concat(mean(h,0), max(h,0))
__global__ void pool_k(const float* __restrict__ h, float* __restrict__ pool) {
    int c = blockIdx.x, t = threadIdx.x;
    if (c < HDIM) {
        float s = 0.f;
        for (int r = t; r < NN; r += 256) s += h[(size_t)r * HDIM + c];
        s = blkSum(s);
        if (t == 0) pool[c] = s * (1.f / NN);
    } else {
        int cc = c - HDIM;
        float m = -3.4e38f;
        for (int r = t; r < NN; r += 256) m = fmaxf(m, h[(size_t)r * HDIM + cc]);
        m = blkMax(m);
        if (t == 0) pool[c] = m;
    }
}

__global__ void fc1_k(const float* __restrict__ pool, const float* __restrict__ W,
                      const float* __restrict__ b, float* __restrict__ z) {
    int o = blockIdx.x, t = threadIdx.x;
    float s = 0.f;
    for (int i = t; i < 2 * HDIM; i += 256) s += pool[i] * W[(size_t)i * HDIM + o];
    s = blkSum(s);
    if (t == 0) z[o] = fmaxf(s + b[o], 0.f);
}

__global__ void fc2_k(const float* __restrict__ z, const float* __restrict__ W,
                      const float* __restrict__ b, float* __restrict__ out) {
    int o = blockIdx.x, t = threadIdx.x;
    float s = 0.f;
    for (int i = t; i < HDIM; i += 256) s += z[i] * W[(size_t)i * OUTD + o];
    s = blkSum(s);
    if (t == 0) out[o] = s + b[o];
}

// ---------------- host side ----------------
static float* sym(const void* s) {
    void* p = nullptr;
    cudaGetSymbolAddress(&p, (const void*)s);
    return (float*)p;
}

#define BIG   128,128,64,32
#define NODE  64,128,32,32

template<int BM,int BN,int WM,int WN,int TRANSB,int SPLITK,int STAGES>
static void launch_tg(dim3 grid,
                      const float* A, int lda, long long sA,
                      const float* B, int ldb, long long sB,
                      float* C, int ldc, long long sC, int K,
                      const float* bias, int act,
                      const float* rowScale, long long sRS)
{
    constexpr size_t sm = tg_smem<BM, BN, TRANSB, STAGES>();
    static bool attr_done = false;
    if (!attr_done) {
        cudaFuncSetAttribute(tgemm_k<BM,BN,WM,WN,TRANSB,SPLITK,STAGES>,
                             cudaFuncAttributeMaxDynamicSharedMemorySize, (int)sm);
        attr_done = true;
    }
    tgemm_k<BM,BN,WM,WN,TRANSB,SPLITK,STAGES><<<grid, 256, sm>>>(
        A, lda, sA, B, ldb, sB, C, ldc, sC, K, bias, act, rowScale, sRS);
}

extern "C" void kernel_launch(void* const* d_in, const int* in_sizes, int n_in,
                              void* d_out, int out_size) {
    const float* x    = (const float*)d_in[0];
    const int*   ei   = (const int*)  d_in[1];
    const int*   ct   = (const int*)  d_in[2];
    const float* Wi   = (const float*)d_in[3];
    const float* bi   = (const float*)d_in[4];
    const float* Wq   = (const float*)d_in[5];
    const float* bq   = (const float*)d_in[6];
    const float* Wk   = (const float*)d_in[7];
    const float* bk   = (const float*)d_in[8];
    const float* Wv   = (const float*)d_in[9];
    const float* bv   = (const float*)d_in[10];
    const float* Bc   = (const float*)d_in[11];
    const float* cemb = (const float*)d_in[12];
    const float* Win  = (const float*)d_in[13];
    const float* binp = (const float*)d_in[14];
    const float* Wo   = (const float*)d_in[15];
    const float* bo   = (const float*)d_in[16];
    const float* Wm1  = (const float*)d_in[17];
    const float* bm1  = (const float*)d_in[18];
    const float* Wm2  = (const float*)d_in[19];
    const float* bm2  = (const float*)d_in[20];
    const float* Wm3  = (const float*)d_in[21];
    const float* bm3  = (const float*)d_in[22];
    const float* lng  = (const float*)d_in[23];
    const float* lnb  = (const float*)d_in[24];
    const float* Wc1  = (const float*)d_in[25];
    const float* bc1  = (const float*)d_in[26];
    const float* Wc2  = (const float*)d_in[27];
    const float* bc2  = (const float*)d_in[28];
    float* out = (float*)d_out;

    float* h    = sym(g_h);
    float* Qt   = sym(g_Qt);
    float* Kt   = sym(g_Kt);
    float* Q    = sym(g_Q);
    float* K    = sym(g_K);
    float* V    = sym(g_V);
    float* S    = sym(g_S);
    float* rs   = sym(g_rs);
    float* gatt = sym(g_gatt);
    float* mq   = sym(g_mq);
    float* mk   = sym(g_mk);
    float* mv   = sym(g_mv);
    float* mo   = sym(g_mo);
    float* mha  = sym(g_mha);
    float* eA   = sym(g_eA);
    float* eB   = sym(g_eB);
    float* m1   = sym(g_m1);
    float* m2   = sym(g_m2);
    float* agg  = sym(g_agg);
    float* pool = sym(g_pool);
    float* z    = sym(g_z);
    unsigned* mask = (unsigned*)sym(g_mask);

    const int TPB = 256;

    static bool flash_attr = false;
    if (!flash_attr) {
        cudaFuncSetAttribute(flash_mha_k,
                             cudaFuncAttributeMaxDynamicSharedMemorySize, FLASH_SMEM);
        flash_attr = true;
    }

    // adjacency mask
    zero_u32_k<<<(NN * MW + TPB - 1) / TPB, TPB>>>(mask, NN * MW);
    build_mask_k<<<(EE + TPB - 1) / TPB, TPB>>>(ei, mask);

    // h = relu(x @ Wi + bi)
    launch_tg<NODE,0,1,3>(dim3(HDIM/128, NN/64, 1),
        x, IND, 0, Wi, HDIM, 0, h, HDIM, 0, IND, bi, 1, nullptr, 0);

    for (int l = 0; l < LL; l++) {
        const float* Wq_l  = Wq  + (size_t)l * HDIM * QD;
        const float* Wk_l  = Wk  + (size_t)l * HDIM * QD;
        const float* Wv_l  = Wv  + (size_t)l * HDIM * QD;
        const float* Bc_l  = Bc  + (size_t)l * QD * QD;
        const float* ce_l  = cemb + (size_t)l * 50 * QD;
        const float* Win_l = Win + (size_t)l * QD * 3 * QD;
        const float* bin_l = binp + (size_t)l * 3 * QD;
        const float* Wo_l  = Wo  + (size_t)l * QD * QD;
        const float* Wm1_l = Wm1 + (size_t)l * (2 * HDIM + QD) * QD;
        const float* Wm2_l = Wm2 + (size_t)l * QD * QD;
        const float* Wm3_l = Wm3 + (size_t)l * QD * HDIM;

        dim3 gNode(QD/128, NN/64, 1);

        // Q/K/V projections
        launch_tg<NODE,0,1,3>(gNode, h, HDIM, 0, Wq_l, QD, 0, Qt, QD, 0,
                              HDIM, bq + l * QD, 0, nullptr, 0);
        launch_tg<NODE,0,1,3>(gNode, h, HDIM, 0, Wk_l, QD, 0, Kt, QD, 0,
                              HDIM, bk + l * QD, 0, nullptr, 0);
        launch_tg<NODE,0,1,3>(gNode, h, HDIM, 0, Wv_l, QD, 0, V, QD, 0,
                              HDIM, bv + l * QD, 0, nullptr, 0);
        // biological constraint: Q = Qt@Bc, K = Kt@Bc^T
        launch_tg<NODE,0,1,3>(gNode, Qt, QD, 0, Bc_l, QD, 0, Q, QD, 0,
                              QD, nullptr, 0, nullptr, 0);
        launch_tg<NODE,1,1,3>(gNode, Kt, QD, 0, Bc_l, QD, 0, K, QD, 0,
                              QD, nullptr, 0, nullptr, 0);
        add_ce_k<<<(NN * QD / 4 + TPB - 1) / TPB, TPB>>>((float4*)Q, (float4*)K,
                                                         (const float4*)ce_l, ct);

        // graph-masked dense attention
        launch_tg<BIG,1,1,3>(dim3(NN/128, NN/128, 1),
            Q, QD, 0, K, QD, 0, S, NN, 0, QD, nullptr, 0, nullptr, 0);
        masked_softmax_k<<<NN, 256>>>(S, mask, rs, 0.0625f);          // 1/sqrt(256)
        zero_f32_k<<<(NN * QD + TPB - 1) / TPB, TPB>>>(gatt, NN * QD);
        launch_tg<BIG,0,4,3>(dim3(QD/128, NN/128, 4),
            S, NN, 0, V, QD, 0, gatt, QD, 0, NN, nullptr, 0, rs, 0);

        // MHA input projections
        launch_tg<NODE,0,1,3>(gNode, Q, QD, 0, Win_l, 3*QD, 0, mq, QD, 0,
                              QD, bin_l, 0, nullptr, 0);
        launch_tg<NODE,0,1,3>(gNode, K, QD, 0, Win_l + QD, 3*QD, 0, mk, QD, 0,
                              QD, bin_l + QD, 0, nullptr, 0);
        launch_tg<NODE,0,1,3>(gNode, V, QD, 0, Win_l + 2*QD, 3*QD, 0, mv, QD, 0,
                              QD, bin_l + 2*QD, 0, nullptr, 0);

        // fused flash MHA (replaces head-scores GEMM + softmax + attn@V)
        flash_mha_k<<<dim3(NN/FBQ, NHD), 256, FLASH_SMEM>>>(
            mq, mk, mv, mo, 0.17677669529663687f);                    // 1/sqrt(32)

        launch_tg<NODE,0,1,3>(gNode, mo, QD, 0, Wo_l, QD, 0, mha, QD, 0,
                              QD, bo + l * QD, 0, nullptr, 0);

        // edge message MLP (first layer factored through node GEMMs)
        launch_tg<NODE,0,1,3>(gNode, h, HDIM, 0, Wm1_l, QD, 0, eA, QD, 0,
                              HDIM, nullptr, 0, nullptr, 0);
        launch_tg<NODE,0,1,3>(gNode, h, HDIM, 0, Wm1_l + HDIM * QD, QD, 0,
                              eB, QD, 0, HDIM, nullptr, 0, nullptr, 0);
        edge_m1_k<<<(EE * QD / 4 + TPB - 1) / TPB, TPB>>>(
            (const float4*)eA, (const float4*)eB, ei, (const float4*)(bm1 + l * QD),
            (float4*)m1);
        launch_tg<BIG,0,1,3>(dim3(QD/128, EE/128, 1),
            m1, QD, 0, Wm2_l, QD, 0, m2, QD, 0, QD, bm2 + l * QD, 1, nullptr, 0);
        launch_tg<BIG,0,1,3>(dim3(HDIM/128, EE/128, 1),
            m2, QD, 0, Wm3_l, HDIM, 0, m1, HDIM, 0, QD, bm3 + l * HDIM, 0, nullptr, 0);
        zero_f32_k<<<(NN * HDIM + TPB - 1) / TPB, TPB>>>(agg, NN * HDIM);
        scatter_k<<<(EE * HDIM / 4 + TPB - 1) / TPB, TPB>>>((const float4*)m1, ei, agg);

        // residual + aggregate + LN
        combine_ln_k<<<NN, HDIM>>>(h, agg, mha, gatt, lng + l * HDIM, lnb + l * HDIM);
    }

    // readout
    pool_k<<<2 * HDIM, 256>>>(h, pool);
    fc1_k<<<HDIM, 256>>>(pool, Wc1, bc1, z);
    fc2_k<<<OUTD, 256>>>(z, Wc2, bc2, out);
}

// round 7
// speedup vs baseline: 8.4752x; 1.2725x over previous
#include <cuda_runtime.h>
#include <math.h>

// ---------------- problem constants ----------------
#define NN   4096
#define EE   65536
#define IND  512
#define HDIM 256
#define QD   256
#define NHD  8
#define HD   32
#define OUTD 10
#define LL   2
#define MW   (NN/32)   // mask words per row
#define NNQD ((long long)NN*QD)

// ---------------- static scratch (device globals; no runtime alloc) ----------------
__device__ float    g_h   [NN*HDIM];
__device__ float    g_bufA[3*NN*QD];     // Qt, Kt, V
__device__ float    g_bufB[3*NN*QD];     // Q, K, V  (post-Bc / copy)
__device__ float    g_bufC[3*NN*QD];     // mq, mk, mv
__device__ float    g_bufD[2*NN*QD];     // eA, eB
__device__ float    g_W3  [2*3*HDIM*QD]; // staged Wq|Wk|Wv per layer
__device__ float    g_b3  [2*3*QD];      // staged bq|bk|bv per layer
__device__ float    g_vm  [QD];          // per-layer V column means
__device__ float    g_gatt[NN*QD];
__device__ float    g_mo  [NN*QD];
__device__ float    g_mha [NN*QD];
__device__ float    g_m1  [(size_t)EE*QD];   // 64MB (also reused for m3)
__device__ float    g_m2  [(size_t)EE*QD];   // 64MB
__device__ unsigned g_mask[(size_t)NN*MW];
__device__ float    g_agg [NN*HDIM];
__device__ float    g_pool[2*HDIM];
__device__ float    g_z   [HDIM];

// ---------------- TF32 helpers ----------------
__device__ __forceinline__ unsigned f2tf(float f) {
    unsigned u;
    asm("cvt.rna.tf32.f32 %0, %1;" : "=r"(u) : "f"(f));
    return u;
}
__device__ __forceinline__ void mma_tf32(float* c, const unsigned* a, const unsigned* b) {
    asm volatile(
        "mma.sync.aligned.m16n8k8.row.col.f32.tf32.tf32.f32 "
        "{%0,%1,%2,%3}, {%4,%5,%6,%7}, {%8,%9}, {%0,%1,%2,%3};"
        : "+f"(c[0]), "+f"(c[1]), "+f"(c[2]), "+f"(c[3])
        : "r"(a[0]), "r"(a[1]), "r"(a[2]), "r"(a[3]), "r"(b[0]), "r"(b[1]));
}
__device__ __forceinline__ void cpasync16(void* sdst, const void* gsrc) {
    unsigned sa = (unsigned)__cvta_generic_to_shared(sdst);
    asm volatile("cp.async.cg.shared.global [%0], [%1], 16;\n" :: "r"(sa), "l"(gsrc));
}
#define CP_COMMIT() asm volatile("cp.async.commit_group;\n" ::: "memory")

// =====================================================================
// TF32 tensor-core GEMM, cp.async pipeline.
//  C[M,N] = act( A[M,K] * op(B) + bias ) * rowScale ; batched via blockIdx.z
//  (strides sA/sB/sC/sBias), or SPLITK>1 for K-split atomic output.
// =====================================================================
template<int BM, int BN, int TRANSB, int STAGES>
constexpr size_t tg_smem() {
    return (size_t)STAGES * ((size_t)BM * 36 + (TRANSB ? (size_t)BN * 36
                                                       : (size_t)32 * (BN + 8))) * 4;
}

template<int BM, int BN, int WM, int WN, int TRANSB, int SPLITK, int STAGES>
__global__ __launch_bounds__(256)
void tgemm_k(const float* __restrict__ A, int lda, long long sA,
             const float* __restrict__ B, int ldb, long long sB,
             float* __restrict__ C, int ldc, long long sC,
             int K,
             const float* __restrict__ bias, long long sBias, int act,
             const float* __restrict__ rowScale, long long sRS)
{
    constexpr int BK   = 32;
    constexpr int WX   = BN / WN;
    constexpr int WY   = BM / WM;
    static_assert(WX * WY == 8, "8 warps");
    constexpr int MM   = WM / 16;
    constexpr int MN   = WN / 8;
    constexpr int AL   = BM * (BK / 4) / 256;
    constexpr int BLt  = BN * (BK / 4) / 256;
    constexpr int BLn  = BK * (BN / 4) / 256;
    constexpr int ASTR = BK + 4;
    constexpr int BNSTR= BN + 8;
    constexpr int ASZ  = BM * ASTR;
    constexpr int BSZ  = TRANSB ? BN * ASTR : BK * BNSTR;

    const int tid  = threadIdx.x;
    const int wid  = tid >> 5;
    const int lane = tid & 31;
    const int wx   = wid % WX;
    const int wy   = wid / WX;
    const int lg   = lane >> 2;
    const int lt   = lane & 3;
    const int m0   = blockIdx.y * BM;
    const int n0   = blockIdx.x * BN;

    const float* Ab;
    const float* Bb;
    float*       Cb;
    const float* biasb;
    const float* rsb;
    int kbeg, kend;
    if (SPLITK > 1) {
        Ab = A; Bb = B; Cb = C; rsb = rowScale; biasb = bias;
        int kc = K / SPLITK;
        kbeg = blockIdx.z * kc;
        kend = kbeg + kc;
    } else {
        Ab    = A + sA * blockIdx.z;
        Bb    = B + sB * blockIdx.z;
        Cb    = C + sC * blockIdx.z;
        biasb = bias ? bias + sBias * blockIdx.z : nullptr;
        rsb   = rowScale ? rowScale + sRS * blockIdx.z : nullptr;
        kbeg = 0; kend = K;
    }

    extern __shared__ float smem[];
    float* AsBase = smem;
    float* BsBase = smem + (size_t)STAGES * ASZ;

    auto load_stage = [&](int s, int k0) {
        float* as = AsBase + (size_t)s * ASZ;
#pragma unroll
        for (int j = 0; j < AL; j++) {
            int idx = tid + j * 256;
            int m   = idx >> 3;
            int k4  = idx & 7;
            cpasync16(&as[m * ASTR + k4 * 4],
                      &Ab[(size_t)(m0 + m) * lda + k0 + k4 * 4]);
        }
        float* bs = BsBase + (size_t)s * BSZ;
        if (TRANSB) {
#pragma unroll
            for (int j = 0; j < BLt; j++) {
                int idx = tid + j * 256;
                int n   = idx >> 3;
                int k4  = idx & 7;
                cpasync16(&bs[n * ASTR + k4 * 4],
                          &Bb[(size_t)(n0 + n) * ldb + k0 + k4 * 4]);
            }
        } else {
#pragma unroll
            for (int j = 0; j < BLn; j++) {
                int idx = tid + j * 256;
                int k   = idx / (BN / 4);
                int n4  = idx % (BN / 4);
                cpasync16(&bs[k * BNSTR + n4 * 4],
                          &Bb[(size_t)(k0 + k) * ldb + n0 + n4 * 4]);
            }
        }
    };

    float acc[MM][MN][4];
#pragma unroll
    for (int i = 0; i < MM; i++)
#pragma unroll
        for (int j = 0; j < MN; j++)
#pragma unroll
            for (int c = 0; c < 4; c++) acc[i][j][c] = 0.f;

    const int ktiles = (kend - kbeg) / BK;

#pragma unroll
    for (int s = 0; s < STAGES - 1; s++) {
        if (s < ktiles) load_stage(s, kbeg + s * BK);
        CP_COMMIT();
    }

    for (int t = 0; t < ktiles; t++) {
        asm volatile("cp.async.wait_group %0;\n" :: "n"(STAGES - 2) : "memory");
        __syncthreads();

        int nt = t + STAGES - 1;
        if (nt < ktiles) load_stage(nt % STAGES, kbeg + nt * BK);
        CP_COMMIT();

        const float* as = AsBase + (size_t)(t % STAGES) * ASZ;
        const float* bs = BsBase + (size_t)(t % STAGES) * BSZ;

#pragma unroll
        for (int ks = 0; ks < BK / 8; ks++) {
            const int kk = ks * 8;
            unsigned af[MM][4], bf[MN][2];
#pragma unroll
            for (int i = 0; i < MM; i++) {
                int row = wy * WM + i * 16 + lg;
                af[i][0] = f2tf(as[row * ASTR + kk + lt]);
                af[i][1] = f2tf(as[(row + 8) * ASTR + kk + lt]);
                af[i][2] = f2tf(as[row * ASTR + kk + lt + 4]);
                af[i][3] = f2tf(as[(row + 8) * ASTR + kk + lt + 4]);
            }
#pragma unroll
            for (int j = 0; j < MN; j++) {
                int col = wx * WN + j * 8 + lg;
                if (TRANSB) {
                    bf[j][0] = f2tf(bs[col * ASTR + kk + lt]);
                    bf[j][1] = f2tf(bs[col * ASTR + kk + lt + 4]);
                } else {
                    bf[j][0] = f2tf(bs[(kk + lt) * BNSTR + col]);
                    bf[j][1] = f2tf(bs[(kk + lt + 4) * BNSTR + col]);
                }
            }
#pragma unroll
            for (int i = 0; i < MM; i++)
#pragma unroll
                for (int j = 0; j < MN; j++)
                    mma_tf32(acc[i][j], af[i], bf[j]);
        }
        __syncthreads();
    }

#pragma unroll
    for (int i = 0; i < MM; i++) {
        int mA = m0 + wy * WM + i * 16 + lg;
        int mB = mA + 8;
        float rsA = rsb ? rsb[mA] : 1.f;
        float rsB = rsb ? rsb[mB] : 1.f;
#pragma unroll
        for (int j = 0; j < MN; j++) {
            int n = n0 + wx * WN + j * 8 + lt * 2;
            float b0 = biasb ? biasb[n] : 0.f;
            float b1 = biasb ? biasb[n + 1] : 0.f;
            float v0 = (acc[i][j][0] + b0) * rsA;
            float v1 = (acc[i][j][1] + b1) * rsA;
            float v2 = (acc[i][j][2] + b0) * rsB;
            float v3 = (acc[i][j][3] + b1) * rsB;
            if (act == 1) {
                v0 = fmaxf(v0, 0.f); v1 = fmaxf(v1, 0.f);
                v2 = fmaxf(v2, 0.f); v3 = fmaxf(v3, 0.f);
            }
            if (SPLITK > 1) {
                atomicAdd(&Cb[(size_t)mA * ldc + n],     v0);
                atomicAdd(&Cb[(size_t)mA * ldc + n + 1], v1);
                atomicAdd(&Cb[(size_t)mB * ldc + n],     v2);
                atomicAdd(&Cb[(size_t)mB * ldc + n + 1], v3);
            } else {
                Cb[(size_t)mA * ldc + n]     = v0;
                Cb[(size_t)mA * ldc + n + 1] = v1;
                Cb[(size_t)mB * ldc + n]     = v2;
                Cb[(size_t)mB * ldc + n + 1] = v3;
            }
        }
    }
}

// =====================================================================
// Flash MHA (unchanged from round 6, proven correct)
// =====================================================================
#define FBQ   128
#define FBKV  64
#define QSTR  36
#define KSTR  36
#define VSTR  40
#define PSTR  68
#define FLASH_SMEM ((FBQ*QSTR + 2*FBKV*KSTR + 2*FBKV*VSTR + 8*16*PSTR) * 4)

__global__ __launch_bounds__(256)
void flash_mha_k(const float* __restrict__ mq, const float* __restrict__ mk,
                 const float* __restrict__ mv, float* __restrict__ mo, float scale)
{
    extern __shared__ float sm[];
    float*    Qs = sm;
    float*    Ks = Qs + FBQ * QSTR;
    float*    Vs = Ks + 2 * FBKV * KSTR;
    unsigned* Ps = (unsigned*)(Vs + 2 * FBKV * VSTR);

    const int tid  = threadIdx.x;
    const int wid  = tid >> 5;
    const int lane = tid & 31;
    const int lg   = lane >> 2;
    const int lt   = lane & 3;
    const int hh   = blockIdx.y;
    const int q0   = blockIdx.x * FBQ;

    const float* Qg = mq + (size_t)q0 * QD + hh * HD;
    const float* Kg = mk + hh * HD;
    const float* Vg = mv + hh * HD;

#pragma unroll
    for (int j = 0; j < 4; j++) {
        int idx = tid + j * 256;
        int r = idx >> 3, c4 = idx & 7;
        cpasync16(&Qs[r * QSTR + c4 * 4], &Qg[(size_t)r * QD + c4 * 4]);
    }
    auto loadKV = [&](int s, int kv0) {
        float* ks = Ks + s * FBKV * KSTR;
        float* vs = Vs + s * FBKV * VSTR;
#pragma unroll
        for (int j = 0; j < 2; j++) {
            int idx = tid + j * 256;
            int r = idx >> 3, c4 = idx & 7;
            cpasync16(&ks[r * KSTR + c4 * 4], &Kg[(size_t)(kv0 + r) * QD + c4 * 4]);
        }
#pragma unroll
        for (int j = 0; j < 2; j++) {
            int idx = tid + j * 256;
            int r = idx >> 3, c4 = idx & 7;
            cpasync16(&vs[r * VSTR + c4 * 4], &Vg[(size_t)(kv0 + r) * QD + c4 * 4]);
        }
    };
    loadKV(0, 0);
    CP_COMMIT();

    float O[4][4];
#pragma unroll
    for (int j = 0; j < 4; j++)
#pragma unroll
        for (int c = 0; c < 4; c++) O[j][c] = 0.f;
    float m0r = -3.4e38f, m1r = -3.4e38f;
    float l0 = 0.f, l1 = 0.f;
    unsigned* Pw = Ps + wid * 16 * PSTR;
    const int qrow = wid * 16 + lg;

    const int NT = NN / FBKV;
    for (int t = 0; t < NT; t++) {
        if (t + 1 < NT) loadKV((t + 1) & 1, (t + 1) * FBKV);
        CP_COMMIT();
        asm volatile("cp.async.wait_group 1;\n" ::: "memory");
        __syncthreads();

        const float* ks = Ks + (t & 1) * FBKV * KSTR;
        const float* vs = Vs + (t & 1) * FBKV * VSTR;

        float Sacc[8][4];
#pragma unroll
        for (int n = 0; n < 8; n++)
#pragma unroll
            for (int c = 0; c < 4; c++) Sacc[n][c] = 0.f;
#pragma unroll
        for (int ks8 = 0; ks8 < 4; ks8++) {
            const int kk = ks8 * 8;
            unsigned af[4];
            af[0] = f2tf(Qs[qrow * QSTR + kk + lt]);
            af[1] = f2tf(Qs[(qrow + 8) * QSTR + kk + lt]);
            af[2] = f2tf(Qs[qrow * QSTR + kk + lt + 4]);
            af[3] = f2tf(Qs[(qrow + 8) * QSTR + kk + lt + 4]);
#pragma unroll
            for (int n = 0; n < 8; n++) {
                int col = n * 8 + lg;
                unsigned bf[2];
                bf[0] = f2tf(ks[col * KSTR + kk + lt]);
                bf[1] = f2tf(ks[col * KSTR + kk + lt + 4]);
                mma_tf32(Sacc[n], af, bf);
            }
        }

        float mx0 = -3.4e38f, mx1 = -3.4e38f;
#pragma unroll
        for (int n = 0; n < 8; n++) {
            Sacc[n][0] *= scale; Sacc[n][1] *= scale;
            Sacc[n][2] *= scale; Sacc[n][3] *= scale;
            mx0 = fmaxf(mx0, fmaxf(Sacc[n][0], Sacc[n][1]));
            mx1 = fmaxf(mx1, fmaxf(Sacc[n][2], Sacc[n][3]));
        }
        mx0 = fmaxf(mx0, __shfl_xor_sync(0xffffffffu, mx0, 1));
        mx0 = fmaxf(mx0, __shfl_xor_sync(0xffffffffu, mx0, 2));
        mx1 = fmaxf(mx1, __shfl_xor_sync(0xffffffffu, mx1, 1));
        mx1 = fmaxf(mx1, __shfl_xor_sync(0xffffffffu, mx1, 2));
        float mn0 = fmaxf(m0r, mx0), mn1 = fmaxf(m1r, mx1);
        float a0 = __expf(m0r - mn0), a1 = __expf(m1r - mn1);
        float rs0 = 0.f, rs1 = 0.f;
#pragma unroll
        for (int n = 0; n < 8; n++) {
            float p0 = __expf(Sacc[n][0] - mn0);
            float p1 = __expf(Sacc[n][1] - mn0);
            float p2 = __expf(Sacc[n][2] - mn1);
            float p3 = __expf(Sacc[n][3] - mn1);
            rs0 += p0 + p1; rs1 += p2 + p3;
            int c0 = n * 8 + lt * 2;
            Pw[lg * PSTR + c0]           = f2tf(p0);
            Pw[lg * PSTR + c0 + 1]       = f2tf(p1);
            Pw[(lg + 8) * PSTR + c0]     = f2tf(p2);
            Pw[(lg + 8) * PSTR + c0 + 1] = f2tf(p3);
        }
        rs0 += __shfl_xor_sync(0xffffffffu, rs0, 1);
        rs0 += __shfl_xor_sync(0xffffffffu, rs0, 2);
        rs1 += __shfl_xor_sync(0xffffffffu, rs1, 1);
        rs1 += __shfl_xor_sync(0xffffffffu, rs1, 2);
        l0 = l0 * a0 + rs0;
        l1 = l1 * a1 + rs1;
        m0r = mn0; m1r = mn1;
#pragma unroll
        for (int j = 0; j < 4; j++) {
            O[j][0] *= a0; O[j][1] *= a0;
            O[j][2] *= a1; O[j][3] *= a1;
        }
        __syncwarp();

#pragma unroll
        for (int ks8 = 0; ks8 < 8; ks8++) {
            const int kk = ks8 * 8;
            unsigned af[4];
            af[0] = Pw[lg * PSTR + kk + lt];
            af[1] = Pw[(lg + 8) * PSTR + kk + lt];
            af[2] = Pw[lg * PSTR + kk + lt + 4];
            af[3] = Pw[(lg + 8) * PSTR + kk + lt + 4];
#pragma unroll
            for (int j = 0; j < 4; j++) {
                int col = j * 8 + lg;
                unsigned bf[2];
                bf[0] = f2tf(vs[(kk + lt) * VSTR + col]);
                bf[1] = f2tf(vs[(kk + lt + 4) * VSTR + col]);
                mma_tf32(O[j], af, bf);
            }
        }
        __syncwarp();
        __syncthreads();
    }

    float inv0 = 1.f / l0, inv1 = 1.f / l1;
    const size_t rA = (size_t)(q0 + qrow) * QD + hh * HD;
    const size_t rB = rA + 8 * QD;
#pragma unroll
    for (int j = 0; j < 4; j++) {
        int c = j * 8 + lt * 2;
        mo[rA + c]     = O[j][0] * inv0;
        mo[rA + c + 1] = O[j][1] * inv0;
        mo[rB + c]     = O[j][2] * inv1;
        mo[rB + c + 1] = O[j][3] * inv1;
    }
}

// =====================================================================
// Sparse graph attention: one 128-thread block per query row.
//  Enumerates set bits of mask row (dedup'd adjacency), computes exact
//  softmax over present entries (masked entries underflow to exactly 0
//  in the dense reference), accumulates V. Empty row -> column mean of V
//  (uniform softmax over all-(-1e9) row).
// =====================================================================
__global__ __launch_bounds__(128)
void sparse_gatt_k(const float* __restrict__ Q, const float* __restrict__ K,
                   const float* __restrict__ V, const unsigned* __restrict__ mask,
                   const float* __restrict__ vmean, float* __restrict__ gatt,
                   float scale)
{
    __shared__ int   idxs[NN];      // 16KB worst case (row with 4096 edges)
    __shared__ float sc  [NN];      // 16KB
    __shared__ int   wbase[5];
    __shared__ float red[4];

    const int s    = blockIdx.x;
    const int tid  = threadIdx.x;
    const int wid  = tid >> 5;
    const int lane = tid & 31;

    // gather set-bit column indices, in ascending order
    unsigned w = mask[(size_t)s * MW + tid];       // MW == 128 == blockDim
    int c = __popc(w);
    int pre = c;
#pragma unroll
    for (int o = 1; o < 32; o <<= 1) {
        int v = __shfl_up_sync(0xffffffffu, pre, o);
        if (lane >= o) pre += v;
    }
    if (lane == 31) wbase[wid + 1] = pre;
    __syncthreads();
    if (tid == 0) {
        wbase[0] = 0;
        wbase[2] += wbase[1];
        wbase[3] += wbase[2];
        wbase[4] += wbase[3];
    }
    __syncthreads();
    const int cnt = wbase[4];
    int p = wbase[wid] + pre - c;
    unsigned ww = w;
    while (ww) {
        int b = __ffs(ww) - 1;
        idxs[p++] = tid * 32 + b;
        ww &= ww - 1;
    }
    __syncthreads();

    const int c0 = tid * 2;
    if (cnt == 0) {     // uniform softmax over all -1e9 -> mean of V
        gatt[(size_t)s * QD + c0]     = vmean[c0];
        gatt[(size_t)s * QD + c0 + 1] = vmean[c0 + 1];
        return;
    }

    // scores: warp per edge, lanes cover 8 dims each
    float q[8];
    const float* Qr = Q + (size_t)s * QD;
#pragma unroll
    for (int i = 0; i < 8; i++) q[i] = Qr[lane * 8 + i];
    for (int e = wid; e < cnt; e += 4) {
        const float* Kr = K + (size_t)idxs[e] * QD;
        float d = 0.f;
#pragma unroll
        for (int i = 0; i < 8; i++) d = fmaf(q[i], Kr[lane * 8 + i], d);
#pragma unroll
        for (int o = 16; o; o >>= 1) d += __shfl_xor_sync(0xffffffffu, d, o);
        if (lane == 0) sc[e] = d * scale;
    }
    __syncthreads();

    // softmax over cnt entries
    float mx = -3.4e38f;
    for (int e = tid; e < cnt; e += 128) mx = fmaxf(mx, sc[e]);
#pragma unroll
    for (int o = 16; o; o >>= 1) mx = fmaxf(mx, __shfl_xor_sync(0xffffffffu, mx, o));
    if (lane == 0) red[wid] = mx;
    __syncthreads();
    mx = fmaxf(fmaxf(red[0], red[1]), fmaxf(red[2], red[3]));
    __syncthreads();

    float sum = 0.f;
    for (int e = tid; e < cnt; e += 128) {
        float pe = __expf(sc[e] - mx);
        sc[e] = pe;
        sum += pe;
    }
#pragma unroll
    for (int o = 16; o; o >>= 1) sum += __shfl_xor_sync(0xffffffffu, sum, o);
    if (lane == 0) red[wid] = sum;
    __syncthreads();
    float inv = 1.f / (red[0] + red[1] + red[2] + red[3]);

    // output: each thread owns 2 columns
    float a0 = 0.f, a1 = 0.f;
    for (int e = 0; e < cnt; e++) {
        const float* Vr = V + (size_t)idxs[e] * QD;
        float pe = sc[e];
        a0 = fmaf(pe, Vr[c0], a0);
        a1 = fmaf(pe, Vr[c0 + 1], a1);
    }
    gatt[(size_t)s * QD + c0]     = a0 * inv;
    gatt[(size_t)s * QD + c0 + 1] = a1 * inv;
}

// ---------------- block reductions (256 threads) ----------------
__device__ __forceinline__ float blkMax(float v) {
    __shared__ float sh[8];
#pragma unroll
    for (int o = 16; o; o >>= 1) v = fmaxf(v, __shfl_xor_sync(0xffffffffu, v, o));
    if ((threadIdx.x & 31) == 0) sh[threadIdx.x >> 5] = v;
    __syncthreads();
    if (threadIdx.x < 32) {
        float w = (threadIdx.x < 8) ? sh[threadIdx.x] : -3.4e38f;
#pragma unroll
        for (int o = 4; o; o >>= 1) w = fmaxf(w, __shfl_xor_sync(0xffffffffu, w, o));
        if (threadIdx.x == 0) sh[0] = w;
    }
    __syncthreads();
    float r = sh[0];
    __syncthreads();
    return r;
}
__device__ __forceinline__ float blkSum(float v) {
    __shared__ float sh[8];
#pragma unroll
    for (int o = 16; o; o >>= 1) v += __shfl_xor_sync(0xffffffffu, v, o);
    if ((threadIdx.x & 31) == 0) sh[threadIdx.x >> 5] = v;
    __syncthreads();
    if (threadIdx.x < 32) {
        float w = (threadIdx.x < 8) ? sh[threadIdx.x] : 0.f;
#pragma unroll
        for (int o = 4; o; o >>= 1) w += __shfl_xor_sync(0xffffffffu, w, o);
        if (threadIdx.x == 0) sh[0] = w;
    }
    __syncthreads();
    float r = sh[0];
    __syncthreads();
    return r;
}

// ---------------- elementwise / small kernels ----------------
__global__ void zero_u32_k(unsigned* __restrict__ p, int n) {
    int i = blockIdx.x * blockDim.x + threadIdx.x;
    if (i < n) p[i] = 0u;
}
__global__ void zero_f32_k(float* __restrict__ p, int n) {
    int i = blockIdx.x * blockDim.x + threadIdx.x;
    if (i < n) p[i] = 0.f;
}
__global__ void build_mask_k(const int* __restrict__ ei, unsigned* __restrict__ mask) {
    int e = blockIdx.x * blockDim.x + threadIdx.x;
    if (e >= EE) return;
    int s = ei[e], t = ei[EE + e];
    atomicOr(&mask[(size_t)s * MW + (t >> 5)], 1u << (t & 31));
}
// stage Wq|Wk|Wv and biases into contiguous per-layer buffers (once)
__global__ void stage_qkv_k(const float* __restrict__ Wq, const float* __restrict__ Wk,
                            const float* __restrict__ Wv, const float* __restrict__ bq,
                            const float* __restrict__ bk, const float* __restrict__ bv,
                            float* __restrict__ W3, float* __restrict__ b3) {
    int i = blockIdx.x * blockDim.x + threadIdx.x;
    const int per = HDIM * QD;
    if (i < 2 * per) {
        int l = i / per, r = i % per;
        W3[((size_t)l * 3 + 0) * per + r] = Wq[i];
        W3[((size_t)l * 3 + 1) * per + r] = Wk[i];
        W3[((size_t)l * 3 + 2) * per + r] = Wv[i];
    }
    if (i < 2 * QD) {
        int l = i / QD, r = i % QD;
        b3[(l * 3 + 0) * QD + r] = bq[i];
        b3[(l * 3 + 1) * QD + r] = bk[i];
        b3[(l * 3 + 2) * QD + r] = bv[i];
    }
}
__global__ void copy4_k(const float4* __restrict__ src, float4* __restrict__ dst, int n) {
    int i = blockIdx.x * blockDim.x + threadIdx.x;
    if (i < n) dst[i] = src[i];
}
__global__ void vmean_k(const float* __restrict__ V, float* __restrict__ vm) {
    int c = blockIdx.x;
    float s = 0.f;
    for (int r = threadIdx.x; r < NN; r += 256) s += V[(size_t)r * QD + c];
    s = blkSum(s);
    if (threadIdx.x == 0) vm[c] = s * (1.f / NN);
}
__global__ void add_ce_k(float4* __restrict__ Q, float4* __restrict__ K,
                         const float4* __restrict__ ce, const int* __restrict__ ct) {
    int idx = blockIdx.x * blockDim.x + threadIdx.x;
    if (idx >= NN * (QD / 4)) return;
    int i = idx >> 6, j4 = idx & 63;
    float4 c = ce[ct[i] * (QD / 4) + j4];
    float4 q = Q[idx], k = K[idx];
    q.x += 0.1f * c.x; q.y += 0.1f * c.y; q.z += 0.1f * c.z; q.w += 0.1f * c.w;
    k.x += 0.1f * c.x; k.y += 0.1f * c.y; k.z += 0.1f * c.z; k.w += 0.1f * c.w;
    Q[idx] = q; K[idx] = k;
}
__global__ void edge_m1_k(const float4* __restrict__ eA, const float4* __restrict__ eB,
                          const int* __restrict__ ei, const float4* __restrict__ bm1,
                          float4* __restrict__ m1) {
    int idx = blockIdx.x * blockDim.x + threadIdx.x;
    if (idx >= EE * (QD / 4)) return;
    int e = idx >> 6, j4 = idx & 63;
    int t = ei[EE + e], s = ei[e];
    float4 a = eA[t * (QD / 4) + j4];
    float4 b = eB[s * (QD / 4) + j4];
    float4 c = bm1[j4];
    float4 r;
    r.x = fmaxf(a.x + b.x + c.x, 0.f);
    r.y = fmaxf(a.y + b.y + c.y, 0.f);
    r.z = fmaxf(a.z + b.z + c.z, 0.f);
    r.w = fmaxf(a.w + b.w + c.w, 0.f);
    m1[idx] = r;
}
__global__ void scatter_k(const float4* __restrict__ m3, const int* __restrict__ ei,
                          float* __restrict__ agg) {
    int idx = blockIdx.x * blockDim.x + threadIdx.x;
    if (idx >= EE * (HDIM / 4)) return;
    int e = idx >> 6, j4 = idx & 63;
    float4 v = m3[idx];
    float* dst = agg + (size_t)ei[EE + e] * HDIM + j4 * 4;
    atomicAdd(dst + 0, v.x);
    atomicAdd(dst + 1, v.y);
    atomicAdd(dst + 2, v.z);
    atomicAdd(dst + 3, v.w);
}
__global__ void combine_ln_k(float* __restrict__ h, const float* __restrict__ agg,
                             const float* __restrict__ mha, const float* __restrict__ gatt,
                             const float* __restrict__ g, const float* __restrict__ b) {
    int r = blockIdx.x, j = threadIdx.x;
    size_t idx = (size_t)r * HDIM + j;
    float v = h[idx] + agg[idx] + mha[idx] + gatt[idx];
    float mu = blkSum(v) * (1.f / HDIM);
    float d = v - mu;
    float var = blkSum(d * d) * (1.f / HDIM);
    h[idx] = d * rsqrtf(var + 1e-5f) * g[j] + b[j];
}
__global__ void pool_k(const float* __restrict__ h, float* __restrict__ pool) {
    int c = blockIdx.x, t = threadIdx.x;
    if (c < HDIM) {
        float s = 0.f;
        for (int r = t; r < NN; r += 256) s += h[(size_t)r * HDIM + c];
        s = blkSum(s);
        if (t == 0) pool[c] = s * (1.f / NN);
    } else {
        int cc = c - HDIM;
        float m = -3.4e38f;
        for (int r = t; r < NN; r += 256) m = fmaxf(m, h[(size_t)r * HDIM + cc]);
        m = blkMax(m);
        if (t == 0) pool[c] = m;
    }
}
__global__ void fc1_k(const float* __restrict__ pool, const float* __restrict__ W,
                      const float* __restrict__ b, float* __restrict__ z) {
    int o = blockIdx.x, t = threadIdx.x;
    float s = 0.f;
    for (int i = t; i < 2 * HDIM; i += 256) s += pool[i] * W[(size_t)i * HDIM + o];
    s = blkSum(s);
    if (t == 0) z[o] = fmaxf(s + b[o], 0.f);
}
__global__ void fc2_k(const float* __restrict__ z, const float* __restrict__ W,
                      const float* __restrict__ b, float* __restrict__ out) {
    int o = blockIdx.x, t = threadIdx.x;
    float s = 0.f;
    for (int i = t; i < HDIM; i += 256) s += z[i] * W[(size_t)i * OUTD + o];
    s = blkSum(s);
    if (t == 0) out[o] = s + b[o];
}

// ---------------- host side ----------------
static float* sym(const void* s) {
    void* p = nullptr;
    cudaGetSymbolAddress(&p, (const void*)s);
    return (float*)p;
}

#define BIG   128,128,64,32
#define NODE  64,128,32,32

template<int BM,int BN,int WM,int WN,int TRANSB,int SPLITK,int STAGES>
static void launch_tg(dim3 grid,
                      const float* A, int lda, long long sA,
                      const float* B, int ldb, long long sB,
                      float* C, int ldc, long long sC, int K,
                      const float* bias, long long sBias, int act)
{
    constexpr size_t sm = tg_smem<BM, BN, TRANSB, STAGES>();
    static bool attr_done = false;
    if (!attr_done) {
        cudaFuncSetAttribute(tgemm_k<BM,BN,WM,WN,TRANSB,SPLITK,STAGES>,
                             cudaFuncAttributeMaxDynamicSharedMemorySize, (int)sm);
        attr_done = true;
    }
    tgemm_k<BM,BN,WM,WN,TRANSB,SPLITK,STAGES><<<grid, 256, sm>>>(
        A, lda, sA, B, ldb, sB, C, ldc, sC, K, bias, sBias, act, nullptr, 0);
}

extern "C" void kernel_launch(void* const* d_in, const int* in_sizes, int n_in,
                              void* d_out, int out_size) {
    const float* x    = (const float*)d_in[0];
    const int*   ei   = (const int*)  d_in[1];
    const int*   ct   = (const int*)  d_in[2];
    const float* Wi   = (const float*)d_in[3];
    const float* bi   = (const float*)d_in[4];
    const float* Wq   = (const float*)d_in[5];
    const float* bq   = (const float*)d_in[6];
    const float* Wk   = (const float*)d_in[7];
    const float* bk   = (const float*)d_in[8];
    const float* Wv   = (const float*)d_in[9];
    const float* bv   = (const float*)d_in[10];
    const float* Bc   = (const float*)d_in[11];
    const float* cemb = (const float*)d_in[12];
    const float* Win  = (const float*)d_in[13];
    const float* binp = (const float*)d_in[14];
    const float* Wo   = (const float*)d_in[15];
    const float* bo   = (const float*)d_in[16];
    const float* Wm1  = (const float*)d_in[17];
    const float* bm1  = (const float*)d_in[18];
    const float* Wm2  = (const float*)d_in[19];
    const float* bm2  = (const float*)d_in[20];
    const float* Wm3  = (const float*)d_in[21];
    const float* bm3  = (const float*)d_in[22];
    const float* lng  = (const float*)d_in[23];
    const float* lnb  = (const float*)d_in[24];
    const float* Wc1  = (const float*)d_in[25];
    const float* bc1  = (const float*)d_in[26];
    const float* Wc2  = (const float*)d_in[27];
    const float* bc2  = (const float*)d_in[28];
    float* out = (float*)d_out;

    float* h    = sym(g_h);
    float* bufA = sym(g_bufA);
    float* bufB = sym(g_bufB);
    float* bufC = sym(g_bufC);
    float* bufD = sym(g_bufD);
    float* W3   = sym(g_W3);
    float* b3   = sym(g_b3);
    float* vm   = sym(g_vm);
    float* gatt = sym(g_gatt);
    float* mo   = sym(g_mo);
    float* mha  = sym(g_mha);
    float* m1   = sym(g_m1);
    float* m2   = sym(g_m2);
    float* agg  = sym(g_agg);
    float* pool = sym(g_pool);
    float* z    = sym(g_z);
    unsigned* mask = (unsigned*)sym(g_mask);

    const int TPB = 256;

    static bool flash_attr = false;
    if (!flash_attr) {
        cudaFuncSetAttribute(flash_mha_k,
                             cudaFuncAttributeMaxDynamicSharedMemorySize, FLASH_SMEM);
        flash_attr = true;
    }

    // adjacency mask + staged QKV weights
    zero_u32_k<<<(NN * MW + TPB - 1) / TPB, TPB>>>(mask, NN * MW);
    build_mask_k<<<(EE + TPB - 1) / TPB, TPB>>>(ei, mask);
    stage_qkv_k<<<(2 * HDIM * QD + TPB - 1) / TPB, TPB>>>(Wq, Wk, Wv, bq, bk, bv, W3, b3);

    // h = relu(x @ Wi + bi)
    launch_tg<NODE,0,1,3>(dim3(HDIM/128, NN/64, 1),
        x, IND, 0, Wi, HDIM, 0, h, HDIM, 0, IND, bi, 0, 1);

    for (int l = 0; l < LL; l++) {
        const float* Bc_l  = Bc  + (size_t)l * QD * QD;
        const float* ce_l  = cemb + (size_t)l * 50 * QD;
        const float* Win_l = Win + (size_t)l * QD * 3 * QD;
        const float* bin_l = binp + (size_t)l * 3 * QD;
        const float* Wo_l  = Wo  + (size_t)l * QD * QD;
        const float* Wm1_l = Wm1 + (size_t)l * (2 * HDIM + QD) * QD;
        const float* Wm2_l = Wm2 + (size_t)l * QD * QD;
        const float* Wm3_l = Wm3 + (size_t)l * QD * HDIM;

        dim3 gNode(QD/128, NN/64, 1);

        // batched Q/K/V projections -> bufA {Qt, Kt, V}
        launch_tg<NODE,0,1,3>(dim3(QD/128, NN/64, 3),
            h, HDIM, 0, W3 + (size_t)l * 3 * HDIM * QD, QD, (long long)HDIM * QD,
            bufA, QD, NNQD, HDIM, b3 + l * 3 * QD, QD, 0);
        // biological constraint: Q = Qt@Bc -> bufB[0], K = Kt@Bc^T -> bufB[1]
        launch_tg<NODE,0,1,3>(gNode, bufA, QD, 0, Bc_l, QD, 0, bufB, QD, 0,
                              QD, nullptr, 0, 0);
        launch_tg<NODE,1,1,3>(gNode, bufA + NNQD, QD, 0, Bc_l, QD, 0, bufB + NNQD, QD, 0,
                              QD, nullptr, 0, 0);
        // V copy into bufB[2] (for contiguous batched mqkv)
        copy4_k<<<(NN * QD / 4 + TPB - 1) / TPB, TPB>>>(
            (const float4*)(bufA + 2 * NNQD), (float4*)(bufB + 2 * NNQD), NN * QD / 4);
        // + 0.1 * cell-type embedding on Q, K
        add_ce_k<<<(NN * QD / 4 + TPB - 1) / TPB, TPB>>>(
            (float4*)bufB, (float4*)(bufB + NNQD), (const float4*)ce_l, ct);

        // sparse graph-masked attention (exact)
        vmean_k<<<QD, 256>>>(bufB + 2 * NNQD, vm);
        sparse_gatt_k<<<NN, 128>>>(bufB, bufB + NNQD, bufB + 2 * NNQD, mask, vm,
                                   gatt, 0.0625f);                   // 1/sqrt(256)

        // batched MHA input projections: bufC {mq, mk, mv}
        launch_tg<NODE,0,1,3>(dim3(QD/128, NN/64, 3),
            bufB, QD, NNQD, Win_l, 3*QD, QD,
            bufC, QD, NNQD, QD, bin_l, QD, 0);

        // fused flash MHA
        flash_mha_k<<<dim3(NN/FBQ, NHD), 256, FLASH_SMEM>>>(
            bufC, bufC + NNQD, bufC + 2 * NNQD, mo, 0.17677669529663687f); // 1/sqrt(32)

        launch_tg<NODE,0,1,3>(gNode, mo, QD, 0, Wo_l, QD, 0, mha, QD, 0,
                              QD, bo + l * QD, 0, 0);

        // batched edge-MLP first layer: bufD {eA, eB}
        launch_tg<NODE,0,1,3>(dim3(QD/128, NN/64, 2),
            h, HDIM, 0, Wm1_l, QD, (long long)HDIM * QD,
            bufD, QD, NNQD, HDIM, nullptr, 0, 0);
        edge_m1_k<<<(EE * QD / 4 + TPB - 1) / TPB, TPB>>>(
            (const float4*)bufD, (const float4*)(bufD + NNQD), ei,
            (const float4*)(bm1 + l * QD), (float4*)m1);
        launch_tg<BIG,0,1,3>(dim3(QD/128, EE/128, 1),
            m1, QD, 0, Wm2_l, QD, 0, m2, QD, 0, QD, bm2 + l * QD, 0, 1);
        launch_tg<BIG,0,1,3>(dim3(HDIM/128, EE/128, 1),
            m2, QD, 0, Wm3_l, HDIM, 0, m1, HDIM, 0, QD, bm3 + l * HDIM, 0, 0);
        zero_f32_k<<<(NN * HDIM + TPB - 1) / TPB, TPB>>>(agg, NN * HDIM);
        scatter_k<<<(EE * HDIM / 4 + TPB - 1) / TPB, TPB>>>((const float4*)m1, ei, agg);

        // residual + aggregate + LN
        combine_ln_k<<<NN, HDIM>>>(h, agg, mha, gatt, lng + l * HDIM, lnb + l * HDIM);
    }

    // readout
    pool_k<<<2 * HDIM, 256>>>(h, pool);
    fc1_k<<<HDIM, 256>>>(pool, Wc1, bc1, z);
    fc2_k<<<OUTD, 256>>>(z, Wc2, bc2, out);
}